// round 1
// baseline (speedup 1.0000x reference)
#include <cuda_runtime.h>
#include <cuda_bf16.h>

// ---------------------------------------------------------------------------
// MultiHeadAttention baseline (round 0): fp32 SIMT, correctness-first.
// Pipeline: LN -> Q/K/V proj -> scores (batched, alpha=1/8) -> softmax ->
//           ctx (batched) -> out proj + bias + residual.
// Scratch via __device__ globals (no allocations anywhere).
// ---------------------------------------------------------------------------

#define HIDDEN 1024
#define SEQ    2048
#define BATCH  2
#define HEADS  16
#define HEADD  64
#define ROWS   (BATCH * SEQ)          // 4096

__device__ float g_xn [ROWS * HIDDEN];
__device__ float g_q  [ROWS * HIDDEN];
__device__ float g_k  [ROWS * HIDDEN];
__device__ float g_v  [ROWS * HIDDEN];
__device__ float g_ctx[ROWS * HIDDEN];
__device__ float g_sc [(long long)BATCH * HEADS * SEQ * SEQ];  // 512 MB

// ---------------------------------------------------------------------------
// Block reductions
// ---------------------------------------------------------------------------
__device__ __forceinline__ float blockReduceSum(float v, float* sh) {
    int lane = threadIdx.x & 31, w = threadIdx.x >> 5;
    #pragma unroll
    for (int o = 16; o; o >>= 1) v += __shfl_down_sync(0xFFFFFFFFu, v, o);
    if (lane == 0) sh[w] = v;
    __syncthreads();
    float r = 0.0f;
    if (w == 0) {
        r = (lane < (int)(blockDim.x >> 5)) ? sh[lane] : 0.0f;
        #pragma unroll
        for (int o = 16; o; o >>= 1) r += __shfl_down_sync(0xFFFFFFFFu, r, o);
        if (lane == 0) sh[0] = r;
    }
    __syncthreads();
    r = sh[0];
    __syncthreads();
    return r;
}

__device__ __forceinline__ float blockReduceMax(float v, float* sh) {
    int lane = threadIdx.x & 31, w = threadIdx.x >> 5;
    #pragma unroll
    for (int o = 16; o; o >>= 1) v = fmaxf(v, __shfl_down_sync(0xFFFFFFFFu, v, o));
    if (lane == 0) sh[w] = v;
    __syncthreads();
    float r = -3.4e38f;
    if (w == 0) {
        r = (lane < (int)(blockDim.x >> 5)) ? sh[lane] : -3.4e38f;
        #pragma unroll
        for (int o = 16; o; o >>= 1) r = fmaxf(r, __shfl_down_sync(0xFFFFFFFFu, r, o));
        if (lane == 0) sh[0] = r;
    }
    __syncthreads();
    r = sh[0];
    __syncthreads();
    return r;
}

// ---------------------------------------------------------------------------
// LayerNorm: one block (256 threads) per row of 1024, float4 everywhere.
// ---------------------------------------------------------------------------
__global__ __launch_bounds__(256) void ln_kernel(
    const float* __restrict__ x, const float* __restrict__ g,
    const float* __restrict__ b, float* __restrict__ xn)
{
    __shared__ float sh[32];
    long long row = blockIdx.x;
    const float4 v = ((const float4*)(x + row * HIDDEN))[threadIdx.x];
    float s  = v.x + v.y + v.z + v.w;
    float sq = v.x*v.x + v.y*v.y + v.z*v.z + v.w*v.w;
    s  = blockReduceSum(s,  sh);
    sq = blockReduceSum(sq, sh);
    float mu  = s  * (1.0f / HIDDEN);
    float var = sq * (1.0f / HIDDEN) - mu * mu;
    float inv = rsqrtf(var + 1e-5f);
    float4 gg = ((const float4*)g)[threadIdx.x];
    float4 bb = ((const float4*)b)[threadIdx.x];
    float4 o;
    o.x = (v.x - mu) * inv * gg.x + bb.x;
    o.y = (v.y - mu) * inv * gg.y + bb.y;
    o.z = (v.z - mu) * inv * gg.z + bb.z;
    o.w = (v.w - mu) * inv * gg.w + bb.w;
    ((float4*)(xn + row * HIDDEN))[threadIdx.x] = o;
}

// ---------------------------------------------------------------------------
// Generic strided "C = alpha * A*B (+bias) (+resid)" tiled GEMM.
//   A[i,k] = A[i*rsA + k*csA]   (csA == 1 required)
//   B[k,j] = B[k*rsB + j*csB]   (either rsB==1 or csB==1)
//   C[i,j] = C[i*rsC + j]       (csC == 1 assumed)
// Batched over blockIdx.z: offset = (z/HB)*SB + (z%HB)*SH per operand.
// M % 64 == 0, N % 64 == 0, K % 16 == 0 required (all shapes here comply).
// ---------------------------------------------------------------------------
#define BM 64
#define BN 64
#define BK 16

__global__ __launch_bounds__(256) void gemm_nt_kernel(
    const float* __restrict__ A, const float* __restrict__ B,
    const float* __restrict__ bias, const float* __restrict__ resid,
    float* __restrict__ C,
    int M, int N, int K,
    int rsA, int rsB, int csB, int rsC,
    int HB,
    long long aSB, long long aSH, long long bSB, long long bSH,
    long long cSB, long long cSH,
    float alpha)
{
    __shared__ float As[BK][BM];
    __shared__ float Bs[BK][BN];

    const int z  = blockIdx.z;
    const long long aOff = (long long)(z / HB) * aSB + (long long)(z % HB) * aSH;
    const long long bOff = (long long)(z / HB) * bSB + (long long)(z % HB) * bSH;
    const long long cOff = (long long)(z / HB) * cSB + (long long)(z % HB) * cSH;
    const float* Ab = A + aOff;
    const float* Bb = B + bOff;

    const int tid = threadIdx.x;
    const int tx = tid & 15, ty = tid >> 4;
    const int tx4 = tx * 4, ty4 = ty * 4;
    const int i0 = blockIdx.y * BM, j0 = blockIdx.x * BN;

    // A load mapping (csA==1): each thread grabs a float4 along K
    const int la_i  = tid >> 2;
    const int la_kk = (tid & 3) * 4;
    // B load mapping rsB==1: float4 along K
    const int lbk_j  = tid >> 2;
    const int lbk_kk = (tid & 3) * 4;
    // B load mapping csB==1: float4 along J
    const int lbj_kk = tid >> 4;
    const int lbj_j  = (tid & 15) * 4;

    float acc[4][4];
    #pragma unroll
    for (int ii = 0; ii < 4; ++ii)
        #pragma unroll
        for (int jj = 0; jj < 4; ++jj) acc[ii][jj] = 0.0f;

    for (int k0 = 0; k0 < K; k0 += BK) {
        // --- load A tile ---
        {
            float4 v = *(const float4*)(Ab + (long long)(i0 + la_i) * rsA + (k0 + la_kk));
            As[la_kk + 0][la_i] = v.x;
            As[la_kk + 1][la_i] = v.y;
            As[la_kk + 2][la_i] = v.z;
            As[la_kk + 3][la_i] = v.w;
        }
        // --- load B tile ---
        if (rsB == 1) {
            float4 v = *(const float4*)(Bb + (long long)(k0 + lbk_kk) + (long long)(j0 + lbk_j) * csB);
            Bs[lbk_kk + 0][lbk_j] = v.x;
            Bs[lbk_kk + 1][lbk_j] = v.y;
            Bs[lbk_kk + 2][lbk_j] = v.z;
            Bs[lbk_kk + 3][lbk_j] = v.w;
        } else { // csB == 1
            float4 v = *(const float4*)(Bb + (long long)(k0 + lbj_kk) * rsB + (j0 + lbj_j));
            *(float4*)&Bs[lbj_kk][lbj_j] = v;
        }
        __syncthreads();

        #pragma unroll
        for (int kk = 0; kk < BK; ++kk) {
            float a[4], b[4];
            *(float4*)a = *(const float4*)&As[kk][ty4];
            *(float4*)b = *(const float4*)&Bs[kk][tx4];
            #pragma unroll
            for (int ii = 0; ii < 4; ++ii)
                #pragma unroll
                for (int jj = 0; jj < 4; ++jj)
                    acc[ii][jj] = fmaf(a[ii], b[jj], acc[ii][jj]);
        }
        __syncthreads();
    }

    // --- epilogue: alpha, bias, residual, store (csC == 1) ---
    float4 bb = make_float4(0.f, 0.f, 0.f, 0.f);
    if (bias) bb = *(const float4*)&bias[j0 + tx4];

    #pragma unroll
    for (int ii = 0; ii < 4; ++ii) {
        const int i = i0 + ty4 + ii;
        const long long rowBase = cOff + (long long)i * rsC + (j0 + tx4);
        float4 r;
        r.x = acc[ii][0] * alpha + bb.x;
        r.y = acc[ii][1] * alpha + bb.y;
        r.z = acc[ii][2] * alpha + bb.z;
        r.w = acc[ii][3] * alpha + bb.w;
        if (resid) {
            float4 rr = *(const float4*)&resid[rowBase];
            r.x += rr.x; r.y += rr.y; r.z += rr.z; r.w += rr.w;
        }
        *(float4*)&C[rowBase] = r;
    }
}

// ---------------------------------------------------------------------------
// Row softmax over 2048 elements, one block per row.
// ---------------------------------------------------------------------------
__global__ __launch_bounds__(256) void softmax_kernel(float* __restrict__ s)
{
    __shared__ float sh[32];
    float* r = s + (long long)blockIdx.x * SEQ;
    float4 v0 = ((const float4*)r)[threadIdx.x];
    float4 v1 = ((const float4*)r)[threadIdx.x + 256];
    float m = fmaxf(fmaxf(fmaxf(v0.x, v0.y), fmaxf(v0.z, v0.w)),
                    fmaxf(fmaxf(v1.x, v1.y), fmaxf(v1.z, v1.w)));
    m = blockReduceMax(m, sh);
    float4 e0, e1;
    e0.x = __expf(v0.x - m); e0.y = __expf(v0.y - m);
    e0.z = __expf(v0.z - m); e0.w = __expf(v0.w - m);
    e1.x = __expf(v1.x - m); e1.y = __expf(v1.y - m);
    e1.z = __expf(v1.z - m); e1.w = __expf(v1.w - m);
    float sum = (e0.x + e0.y + e0.z + e0.w) + (e1.x + e1.y + e1.z + e1.w);
    sum = blockReduceSum(sum, sh);
    float inv = 1.0f / sum;
    e0.x *= inv; e0.y *= inv; e0.z *= inv; e0.w *= inv;
    e1.x *= inv; e1.y *= inv; e1.z *= inv; e1.w *= inv;
    ((float4*)r)[threadIdx.x]       = e0;
    ((float4*)r)[threadIdx.x + 256] = e1;
}

// ---------------------------------------------------------------------------
// Launch
// ---------------------------------------------------------------------------
extern "C" void kernel_launch(void* const* d_in, const int* in_sizes, int n_in,
                              void* d_out, int out_size)
{
    (void)in_sizes; (void)n_in; (void)out_size;
    const float* x    = (const float*)d_in[0];
    const float* Wq   = (const float*)d_in[1];
    const float* bq   = (const float*)d_in[2];
    const float* Wk   = (const float*)d_in[3];
    const float* bk   = (const float*)d_in[4];
    const float* Wv   = (const float*)d_in[5];
    const float* bv   = (const float*)d_in[6];
    const float* Wo   = (const float*)d_in[7];
    const float* bo   = (const float*)d_in[8];
    const float* ln_g = (const float*)d_in[9];
    const float* ln_b = (const float*)d_in[10];
    float* out = (float*)d_out;

    float *xn, *q, *k, *v, *ctx, *sc;
    cudaGetSymbolAddress((void**)&xn,  g_xn);
    cudaGetSymbolAddress((void**)&q,   g_q);
    cudaGetSymbolAddress((void**)&k,   g_k);
    cudaGetSymbolAddress((void**)&v,   g_v);
    cudaGetSymbolAddress((void**)&ctx, g_ctx);
    cudaGetSymbolAddress((void**)&sc,  g_sc);

    // 1) LayerNorm
    ln_kernel<<<ROWS, 256>>>(x, ln_g, ln_b, xn);

    // 2) Q/K/V projections: [4096,1024] x W^T  (A: rsA=1024; B=W: rsB=1, csB=1024)
    dim3 gProj(HIDDEN / BN, ROWS / BM, 1);
    gemm_nt_kernel<<<gProj, 256>>>(xn, Wq, bq, nullptr, q,
        ROWS, HIDDEN, HIDDEN, HIDDEN, 1, HIDDEN, HIDDEN,
        1, 0, 0, 0, 0, 0, 0, 1.0f);
    gemm_nt_kernel<<<gProj, 256>>>(xn, Wk, bk, nullptr, k,
        ROWS, HIDDEN, HIDDEN, HIDDEN, 1, HIDDEN, HIDDEN,
        1, 0, 0, 0, 0, 0, 0, 1.0f);
    gemm_nt_kernel<<<gProj, 256>>>(xn, Wv, bv, nullptr, v,
        ROWS, HIDDEN, HIDDEN, HIDDEN, 1, HIDDEN, HIDDEN,
        1, 0, 0, 0, 0, 0, 0, 1.0f);

    // 3) scores[b,h] = (Q_bh @ K_bh^T) / 8 : M=N=2048, K=64, 32 batches
    dim3 gScore(SEQ / BN, SEQ / BM, BATCH * HEADS);
    gemm_nt_kernel<<<gScore, 256>>>(q, k, nullptr, nullptr, sc,
        SEQ, SEQ, HEADD,
        HIDDEN /*rsA*/, 1 /*rsB*/, HIDDEN /*csB*/, SEQ /*rsC*/,
        HEADS,
        (long long)SEQ * HIDDEN, HEADD,                 // A (q)
        (long long)SEQ * HIDDEN, HEADD,                 // B (k)
        (long long)HEADS * SEQ * SEQ, (long long)SEQ * SEQ,  // C (scores)
        0.125f);

    // 4) softmax over last dim
    softmax_kernel<<<BATCH * HEADS * SEQ, 256>>>(sc);

    // 5) ctx[b,h] = attn @ V_bh : M=2048, N=64, K=2048
    dim3 gCtx(HEADD / BN, SEQ / BM, BATCH * HEADS);
    gemm_nt_kernel<<<gCtx, 256>>>(sc, v, nullptr, nullptr, ctx,
        SEQ, HEADD, SEQ,
        SEQ /*rsA*/, HIDDEN /*rsB*/, 1 /*csB*/, HIDDEN /*rsC*/,
        HEADS,
        (long long)HEADS * SEQ * SEQ, (long long)SEQ * SEQ,  // A (attn)
        (long long)SEQ * HIDDEN, HEADD,                      // B (v)
        (long long)SEQ * HIDDEN, HEADD,                      // C (ctx)
        1.0f);

    // 6) out = x + ctx @ Wo^T + bo
    gemm_nt_kernel<<<gProj, 256>>>(ctx, Wo, bo, x, out,
        ROWS, HIDDEN, HIDDEN, HIDDEN, 1, HIDDEN, HIDDEN,
        1, 0, 0, 0, 0, 0, 0, 1.0f);
}

// round 3
// speedup vs baseline: 1.6499x; 1.6499x over previous
#include <cuda_runtime.h>
#include <cuda_bf16.h>

// ---------------------------------------------------------------------------
// MultiHeadAttention round 2: tf32 mma.sync tensor-core GEMMs (unfused).
// LN -> QKV proj (tf32 MMA) -> scores (tf32 MMA, alpha=1/8) -> softmax ->
// ctx (tf32 MMA) -> out proj + bias + residual (tf32 MMA).
// ---------------------------------------------------------------------------

#define HIDDEN 1024
#define SEQ    2048
#define BATCH  2
#define HEADS  16
#define HEADD  64
#define ROWS   (BATCH * SEQ)          // 4096

__device__ float g_xn [ROWS * HIDDEN];
__device__ float g_q  [ROWS * HIDDEN];
__device__ float g_k  [ROWS * HIDDEN];
__device__ float g_v  [ROWS * HIDDEN];
__device__ float g_ctx[ROWS * HIDDEN];
__device__ float g_sc [(long long)BATCH * HEADS * SEQ * SEQ];  // 512 MB

// ---------------------------------------------------------------------------
__device__ __forceinline__ unsigned f2tf(float f) {
    unsigned u;
    asm("cvt.rna.tf32.f32 %0, %1;" : "=r"(u) : "f"(f));
    return u;
}

__device__ __forceinline__ float blockReduceSum(float v, float* sh) {
    int lane = threadIdx.x & 31, w = threadIdx.x >> 5;
    #pragma unroll
    for (int o = 16; o; o >>= 1) v += __shfl_down_sync(0xFFFFFFFFu, v, o);
    if (lane == 0) sh[w] = v;
    __syncthreads();
    float r = 0.0f;
    if (w == 0) {
        r = (lane < (int)(blockDim.x >> 5)) ? sh[lane] : 0.0f;
        #pragma unroll
        for (int o = 16; o; o >>= 1) r += __shfl_down_sync(0xFFFFFFFFu, r, o);
        if (lane == 0) sh[0] = r;
    }
    __syncthreads();
    r = sh[0];
    __syncthreads();
    return r;
}

__device__ __forceinline__ float blockReduceMax(float v, float* sh) {
    int lane = threadIdx.x & 31, w = threadIdx.x >> 5;
    #pragma unroll
    for (int o = 16; o; o >>= 1) v = fmaxf(v, __shfl_down_sync(0xFFFFFFFFu, v, o));
    if (lane == 0) sh[w] = v;
    __syncthreads();
    float r = -3.4e38f;
    if (w == 0) {
        r = (lane < (int)(blockDim.x >> 5)) ? sh[lane] : -3.4e38f;
        #pragma unroll
        for (int o = 16; o; o >>= 1) r = fmaxf(r, __shfl_down_sync(0xFFFFFFFFu, r, o));
        if (lane == 0) sh[0] = r;
    }
    __syncthreads();
    r = sh[0];
    __syncthreads();
    return r;
}

// ---------------------------------------------------------------------------
// LayerNorm: one block (256 threads) per row of 1024.
// ---------------------------------------------------------------------------
__global__ __launch_bounds__(256) void ln_kernel(
    const float* __restrict__ x, const float* __restrict__ g,
    const float* __restrict__ b, float* __restrict__ xn)
{
    __shared__ float sh[32];
    long long row = blockIdx.x;
    const float4 v = ((const float4*)(x + row * HIDDEN))[threadIdx.x];
    float s  = v.x + v.y + v.z + v.w;
    float sq = v.x*v.x + v.y*v.y + v.z*v.z + v.w*v.w;
    s  = blockReduceSum(s,  sh);
    sq = blockReduceSum(sq, sh);
    float mu  = s  * (1.0f / HIDDEN);
    float var = sq * (1.0f / HIDDEN) - mu * mu;
    float inv = rsqrtf(var + 1e-5f);
    float4 gg = ((const float4*)g)[threadIdx.x];
    float4 bb = ((const float4*)b)[threadIdx.x];
    float4 o;
    o.x = (v.x - mu) * inv * gg.x + bb.x;
    o.y = (v.y - mu) * inv * gg.y + bb.y;
    o.z = (v.z - mu) * inv * gg.z + bb.z;
    o.w = (v.w - mu) * inv * gg.w + bb.w;
    ((float4*)(xn + row * HIDDEN))[threadIdx.x] = o;
}

// ---------------------------------------------------------------------------
// tf32 tensor-core GEMM: C = alpha * A*B (+bias) (+resid)
//   A[i,k] = A[i*rsA + k]                       (K-contiguous)
//   BK_CONTIG:  B[k,j] = B[k + j*ldB]           (K-contiguous, e.g. W^T, K^T)
//   !BK_CONTIG: B[k,j] = B[k*ldB + j]           (J-contiguous, e.g. V)
//   C[i,j] = C[i*rsC + j]
// Batched over blockIdx.z like round-1 kernel.
// Block: 256 threads (8 warps, 4x2), tile 128x64x32, warp tile 32x32,
// mma.sync.m16n8k8.tf32. Smem padded [*][BK+4] -> conflict-free frag loads.
// M%128==0, N%64==0, K%32==0 (all shapes comply).
// ---------------------------------------------------------------------------
#define TBM 128
#define TBN 64
#define TBK 32

template<bool BK_CONTIG>
__global__ __launch_bounds__(256) void gemm_tf32_kernel(
    const float* __restrict__ A, const float* __restrict__ B,
    const float* __restrict__ bias, const float* __restrict__ resid,
    float* __restrict__ C,
    int K, int rsA, int ldB, int rsC,
    int HB,
    long long aSB, long long aSH, long long bSB, long long bSH,
    long long cSB, long long cSH, float alpha)
{
    __shared__ unsigned As[TBM][TBK + 4];   // [m][k], pad 4 -> bank = 4*qr+qc
    __shared__ unsigned Bs[TBN][TBK + 4];   // [n][k]

    const int z = blockIdx.z;
    const float* Ab = A + (long long)(z / HB) * aSB + (long long)(z % HB) * aSH;
    const float* Bb = B + (long long)(z / HB) * bSB + (long long)(z % HB) * bSH;
    const long long cOff = (long long)(z / HB) * cSB + (long long)(z % HB) * cSH;

    const int tid  = threadIdx.x;
    const int lane = tid & 31;
    const int wid  = tid >> 5;
    const int wm   = wid & 3;        // warp row (4)
    const int wn   = wid >> 2;       // warp col (2)
    const int qr   = lane >> 2;      // 0..7
    const int qc   = lane & 3;       // 0..3
    const int i0   = blockIdx.y * TBM;
    const int j0   = blockIdx.x * TBN;

    float acc[2][4][4];
    #pragma unroll
    for (int mi = 0; mi < 2; ++mi)
        #pragma unroll
        for (int ni = 0; ni < 4; ++ni)
            #pragma unroll
            for (int r = 0; r < 4; ++r) acc[mi][ni][r] = 0.0f;

    for (int k0 = 0; k0 < K; k0 += TBK) {
        // ---- load A tile 128x32 (4 x float4 per thread, vector STS) ----
        #pragma unroll
        for (int it = 0; it < 4; ++it) {
            int idx = tid + it * 256;
            int row = idx >> 3;
            int kk  = (idx & 7) * 4;
            float4 v = *(const float4*)(Ab + (long long)(i0 + row) * rsA + (k0 + kk));
            *(uint4*)&As[row][kk] =
                make_uint4(f2tf(v.x), f2tf(v.y), f2tf(v.z), f2tf(v.w));
        }
        // ---- load B tile 64x32 ----
        if (BK_CONTIG) {
            #pragma unroll
            for (int it = 0; it < 2; ++it) {
                int idx = tid + it * 256;
                int j  = idx >> 3;
                int kk = (idx & 7) * 4;
                float4 v = *(const float4*)(Bb + (long long)(j0 + j) * ldB + (k0 + kk));
                *(uint4*)&Bs[j][kk] =
                    make_uint4(f2tf(v.x), f2tf(v.y), f2tf(v.z), f2tf(v.w));
            }
        } else {
            #pragma unroll
            for (int it = 0; it < 8; ++it) {
                int idx = tid + it * 256;
                int j = idx & 63;
                int k = idx >> 6;
                Bs[j][k] = f2tf(Bb[(long long)(k0 + k) * ldB + (j0 + j)]);
            }
        }
        __syncthreads();

        // ---- 4 k-steps of m16n8k8 ----
        #pragma unroll
        for (int ks = 0; ks < 4; ++ks) {
            const int kb = ks * 8;
            unsigned a[2][4], b[4][2];
            #pragma unroll
            for (int mi = 0; mi < 2; ++mi) {
                int r = wm * 32 + mi * 16 + qr;
                a[mi][0] = As[r][kb + qc];
                a[mi][1] = As[r + 8][kb + qc];
                a[mi][2] = As[r][kb + qc + 4];
                a[mi][3] = As[r + 8][kb + qc + 4];
            }
            #pragma unroll
            for (int ni = 0; ni < 4; ++ni) {
                int c = wn * 32 + ni * 8 + qr;
                b[ni][0] = Bs[c][kb + qc];
                b[ni][1] = Bs[c][kb + qc + 4];
            }
            #pragma unroll
            for (int mi = 0; mi < 2; ++mi)
                #pragma unroll
                for (int ni = 0; ni < 4; ++ni) {
                    asm volatile(
                        "mma.sync.aligned.m16n8k8.row.col.f32.tf32.tf32.f32 "
                        "{%0,%1,%2,%3},{%4,%5,%6,%7},{%8,%9},{%0,%1,%2,%3};"
                        : "+f"(acc[mi][ni][0]), "+f"(acc[mi][ni][1]),
                          "+f"(acc[mi][ni][2]), "+f"(acc[mi][ni][3])
                        : "r"(a[mi][0]), "r"(a[mi][1]), "r"(a[mi][2]), "r"(a[mi][3]),
                          "r"(b[ni][0]), "r"(b[ni][1]));
                }
        }
        __syncthreads();
    }

    // ---- epilogue: alpha, bias, residual, float2 stores ----
    #pragma unroll
    for (int mi = 0; mi < 2; ++mi) {
        const int r0 = i0 + wm * 32 + mi * 16 + qr;
        #pragma unroll
        for (int ni = 0; ni < 4; ++ni) {
            const int c = j0 + wn * 32 + ni * 8 + qc * 2;
            float bx = 0.f, by = 0.f;
            if (bias) { bx = bias[c]; by = bias[c + 1]; }
            {
                long long off = cOff + (long long)r0 * rsC + c;
                float2 v;
                v.x = acc[mi][ni][0] * alpha + bx;
                v.y = acc[mi][ni][1] * alpha + by;
                if (resid) { float2 rr = *(const float2*)&resid[off];
                             v.x += rr.x; v.y += rr.y; }
                *(float2*)&C[off] = v;
            }
            {
                long long off = cOff + (long long)(r0 + 8) * rsC + c;
                float2 v;
                v.x = acc[mi][ni][2] * alpha + bx;
                v.y = acc[mi][ni][3] * alpha + by;
                if (resid) { float2 rr = *(const float2*)&resid[off];
                             v.x += rr.x; v.y += rr.y; }
                *(float2*)&C[off] = v;
            }
        }
    }
}

// ---------------------------------------------------------------------------
// Row softmax over 2048 elements, one block per row.
// ---------------------------------------------------------------------------
__global__ __launch_bounds__(256) void softmax_kernel(float* __restrict__ s)
{
    __shared__ float sh[32];
    float* r = s + (long long)blockIdx.x * SEQ;
    float4 v0 = ((const float4*)r)[threadIdx.x];
    float4 v1 = ((const float4*)r)[threadIdx.x + 256];
    float m = fmaxf(fmaxf(fmaxf(v0.x, v0.y), fmaxf(v0.z, v0.w)),
                    fmaxf(fmaxf(v1.x, v1.y), fmaxf(v1.z, v1.w)));
    m = blockReduceMax(m, sh);
    float4 e0, e1;
    e0.x = __expf(v0.x - m); e0.y = __expf(v0.y - m);
    e0.z = __expf(v0.z - m); e0.w = __expf(v0.w - m);
    e1.x = __expf(v1.x - m); e1.y = __expf(v1.y - m);
    e1.z = __expf(v1.z - m); e1.w = __expf(v1.w - m);
    float sum = (e0.x + e0.y + e0.z + e0.w) + (e1.x + e1.y + e1.z + e1.w);
    sum = blockReduceSum(sum, sh);
    float inv = 1.0f / sum;
    e0.x *= inv; e0.y *= inv; e0.z *= inv; e0.w *= inv;
    e1.x *= inv; e1.y *= inv; e1.z *= inv; e1.w *= inv;
    ((float4*)r)[threadIdx.x]       = e0;
    ((float4*)r)[threadIdx.x + 256] = e1;
}

// ---------------------------------------------------------------------------
// Launch
// ---------------------------------------------------------------------------
extern "C" void kernel_launch(void* const* d_in, const int* in_sizes, int n_in,
                              void* d_out, int out_size)
{
    (void)in_sizes; (void)n_in; (void)out_size;
    const float* x    = (const float*)d_in[0];
    const float* Wq   = (const float*)d_in[1];
    const float* bq   = (const float*)d_in[2];
    const float* Wk   = (const float*)d_in[3];
    const float* bk   = (const float*)d_in[4];
    const float* Wv   = (const float*)d_in[5];
    const float* bv   = (const float*)d_in[6];
    const float* Wo   = (const float*)d_in[7];
    const float* bo   = (const float*)d_in[8];
    const float* ln_g = (const float*)d_in[9];
    const float* ln_b = (const float*)d_in[10];
    float* out = (float*)d_out;

    float *xn, *q, *k, *v, *ctx, *sc;
    cudaGetSymbolAddress((void**)&xn,  g_xn);
    cudaGetSymbolAddress((void**)&q,   g_q);
    cudaGetSymbolAddress((void**)&k,   g_k);
    cudaGetSymbolAddress((void**)&v,   g_v);
    cudaGetSymbolAddress((void**)&ctx, g_ctx);
    cudaGetSymbolAddress((void**)&sc,  g_sc);

    // 1) LayerNorm
    ln_kernel<<<ROWS, 256>>>(x, ln_g, ln_b, xn);

    // 2) Q/K/V projections: out[i,j] = xn[i,:] . W[j,:]  (B K-contiguous)
    dim3 gProj(HIDDEN / TBN, ROWS / TBM, 1);
    gemm_tf32_kernel<true><<<gProj, 256>>>(xn, Wq, bq, nullptr, q,
        HIDDEN, HIDDEN, HIDDEN, HIDDEN, 1, 0, 0, 0, 0, 0, 0, 1.0f);
    gemm_tf32_kernel<true><<<gProj, 256>>>(xn, Wk, bk, nullptr, k,
        HIDDEN, HIDDEN, HIDDEN, HIDDEN, 1, 0, 0, 0, 0, 0, 0, 1.0f);
    gemm_tf32_kernel<true><<<gProj, 256>>>(xn, Wv, bv, nullptr, v,
        HIDDEN, HIDDEN, HIDDEN, HIDDEN, 1, 0, 0, 0, 0, 0, 0, 1.0f);

    // 3) scores[b,h] = (Q_bh @ K_bh^T) / 8 : M=N=2048, K=64, 32 batches
    //    B = K-matrix, element (kk, j) = K[j*1024 + kk] -> K-contiguous
    dim3 gScore(SEQ / TBN, SEQ / TBM, BATCH * HEADS);
    gemm_tf32_kernel<true><<<gScore, 256>>>(q, k, nullptr, nullptr, sc,
        HEADD, HIDDEN, HIDDEN, SEQ,
        HEADS,
        (long long)SEQ * HIDDEN, HEADD,
        (long long)SEQ * HIDDEN, HEADD,
        (long long)HEADS * SEQ * SEQ, (long long)SEQ * SEQ,
        0.125f);

    // 4) softmax over last dim
    softmax_kernel<<<BATCH * HEADS * SEQ, 256>>>(sc);

    // 5) ctx[b,h] = attn @ V_bh : M=2048, N=64, K=2048 (B J-contiguous)
    dim3 gCtx(HEADD / TBN, SEQ / TBM, BATCH * HEADS);
    gemm_tf32_kernel<false><<<gCtx, 256>>>(sc, v, nullptr, nullptr, ctx,
        SEQ, SEQ, HIDDEN, HIDDEN,
        HEADS,
        (long long)HEADS * SEQ * SEQ, (long long)SEQ * SEQ,
        (long long)SEQ * HIDDEN, HEADD,
        (long long)SEQ * HIDDEN, HEADD,
        1.0f);

    // 6) out = x + ctx @ Wo^T + bo
    gemm_tf32_kernel<true><<<gProj, 256>>>(ctx, Wo, bo, x, out,
        HIDDEN, HIDDEN, HIDDEN, HIDDEN, 1, 0, 0, 0, 0, 0, 0, 1.0f);
}

// round 6
// speedup vs baseline: 2.9941x; 1.8147x over previous
#include <cuda_runtime.h>
#include <cuda_bf16.h>

// ---------------------------------------------------------------------------
// MultiHeadAttention round 6: LN -> QKV proj (tf32 MMA) ->
// fused flash attention (QK^T -> online softmax -> PV, tf32 MMA) ->
// out proj + bias + residual (tf32 MMA).
// Round-5 fix: Q/K tile loads now cover all 128 rows (it<8, was it<4).
// ---------------------------------------------------------------------------

#define HIDDEN 1024
#define SEQ    2048
#define BATCH  2
#define HEADS  16
#define HEADD  64
#define ROWS   (BATCH * SEQ)          // 4096

__device__ float g_xn [ROWS * HIDDEN];
__device__ float g_q  [ROWS * HIDDEN];
__device__ float g_k  [ROWS * HIDDEN];
__device__ float g_v  [ROWS * HIDDEN];
__device__ float g_ctx[ROWS * HIDDEN];

// ---------------------------------------------------------------------------
__device__ __forceinline__ unsigned f2tf(float f) {
    unsigned u;
    asm("cvt.rna.tf32.f32 %0, %1;" : "=r"(u) : "f"(f));
    return u;
}

__device__ __forceinline__ void mma8(float* c,
    unsigned a0, unsigned a1, unsigned a2, unsigned a3,
    unsigned b0, unsigned b1)
{
    asm volatile(
        "mma.sync.aligned.m16n8k8.row.col.f32.tf32.tf32.f32 "
        "{%0,%1,%2,%3},{%4,%5,%6,%7},{%8,%9},{%0,%1,%2,%3};"
        : "+f"(c[0]), "+f"(c[1]), "+f"(c[2]), "+f"(c[3])
        : "r"(a0), "r"(a1), "r"(a2), "r"(a3), "r"(b0), "r"(b1));
}

__device__ __forceinline__ float blockReduceSum(float v, float* sh) {
    int lane = threadIdx.x & 31, w = threadIdx.x >> 5;
    #pragma unroll
    for (int o = 16; o; o >>= 1) v += __shfl_down_sync(0xFFFFFFFFu, v, o);
    if (lane == 0) sh[w] = v;
    __syncthreads();
    float r = 0.0f;
    if (w == 0) {
        r = (lane < (int)(blockDim.x >> 5)) ? sh[lane] : 0.0f;
        #pragma unroll
        for (int o = 16; o; o >>= 1) r += __shfl_down_sync(0xFFFFFFFFu, r, o);
        if (lane == 0) sh[0] = r;
    }
    __syncthreads();
    r = sh[0];
    __syncthreads();
    return r;
}

// ---------------------------------------------------------------------------
// LayerNorm: one block (256 threads) per row of 1024.
// ---------------------------------------------------------------------------
__global__ __launch_bounds__(256) void ln_kernel(
    const float* __restrict__ x, const float* __restrict__ g,
    const float* __restrict__ b, float* __restrict__ xn)
{
    __shared__ float sh[32];
    long long row = blockIdx.x;
    const float4 v = ((const float4*)(x + row * HIDDEN))[threadIdx.x];
    float s  = v.x + v.y + v.z + v.w;
    float sq = v.x*v.x + v.y*v.y + v.z*v.z + v.w*v.w;
    s  = blockReduceSum(s,  sh);
    sq = blockReduceSum(sq, sh);
    float mu  = s  * (1.0f / HIDDEN);
    float var = sq * (1.0f / HIDDEN) - mu * mu;
    float inv = rsqrtf(var + 1e-5f);
    float4 gg = ((const float4*)g)[threadIdx.x];
    float4 bb = ((const float4*)b)[threadIdx.x];
    float4 o;
    o.x = (v.x - mu) * inv * gg.x + bb.x;
    o.y = (v.y - mu) * inv * gg.y + bb.y;
    o.z = (v.z - mu) * inv * gg.z + bb.z;
    o.w = (v.w - mu) * inv * gg.w + bb.w;
    ((float4*)(xn + row * HIDDEN))[threadIdx.x] = o;
}

// ---------------------------------------------------------------------------
// tf32 tensor-core GEMM (projections): C = A*B^T + bias (+resid)
//   A[i,k] = A[i*1024 + k], B = W row-major (K-contiguous per output col).
// Block 256 thr (8 warps 4x2), tile 128x64x32, warp tile 32x32.
// ---------------------------------------------------------------------------
#define TBM 128
#define TBN 64
#define TBK 32

__global__ __launch_bounds__(256) void gemm_tf32_kernel(
    const float* __restrict__ A, const float* __restrict__ B,
    const float* __restrict__ bias, const float* __restrict__ resid,
    float* __restrict__ C, int K)
{
    __shared__ unsigned As[TBM][TBK + 4];
    __shared__ unsigned Bs[TBN][TBK + 4];

    const int tid  = threadIdx.x;
    const int lane = tid & 31;
    const int wid  = tid >> 5;
    const int wm   = wid & 3;
    const int wn   = wid >> 2;
    const int qr   = lane >> 2;
    const int qc   = lane & 3;
    const int i0   = blockIdx.y * TBM;
    const int j0   = blockIdx.x * TBN;

    float acc[2][4][4];
    #pragma unroll
    for (int mi = 0; mi < 2; ++mi)
        #pragma unroll
        for (int ni = 0; ni < 4; ++ni)
            #pragma unroll
            for (int r = 0; r < 4; ++r) acc[mi][ni][r] = 0.0f;

    for (int k0 = 0; k0 < K; k0 += TBK) {
        #pragma unroll
        for (int it = 0; it < 4; ++it) {
            int idx = tid + it * 256;
            int row = idx >> 3;
            int kk  = (idx & 7) * 4;
            float4 v = *(const float4*)(A + (long long)(i0 + row) * HIDDEN + (k0 + kk));
            *(uint4*)&As[row][kk] =
                make_uint4(f2tf(v.x), f2tf(v.y), f2tf(v.z), f2tf(v.w));
        }
        #pragma unroll
        for (int it = 0; it < 2; ++it) {
            int idx = tid + it * 256;
            int j  = idx >> 3;
            int kk = (idx & 7) * 4;
            float4 v = *(const float4*)(B + (long long)(j0 + j) * HIDDEN + (k0 + kk));
            *(uint4*)&Bs[j][kk] =
                make_uint4(f2tf(v.x), f2tf(v.y), f2tf(v.z), f2tf(v.w));
        }
        __syncthreads();

        #pragma unroll
        for (int ks = 0; ks < 4; ++ks) {
            const int kb = ks * 8;
            unsigned a[2][4], b[4][2];
            #pragma unroll
            for (int mi = 0; mi < 2; ++mi) {
                int r = wm * 32 + mi * 16 + qr;
                a[mi][0] = As[r][kb + qc];
                a[mi][1] = As[r + 8][kb + qc];
                a[mi][2] = As[r][kb + qc + 4];
                a[mi][3] = As[r + 8][kb + qc + 4];
            }
            #pragma unroll
            for (int ni = 0; ni < 4; ++ni) {
                int c = wn * 32 + ni * 8 + qr;
                b[ni][0] = Bs[c][kb + qc];
                b[ni][1] = Bs[c][kb + qc + 4];
            }
            #pragma unroll
            for (int mi = 0; mi < 2; ++mi)
                #pragma unroll
                for (int ni = 0; ni < 4; ++ni)
                    mma8(acc[mi][ni], a[mi][0], a[mi][1], a[mi][2], a[mi][3],
                         b[ni][0], b[ni][1]);
        }
        __syncthreads();
    }

    #pragma unroll
    for (int mi = 0; mi < 2; ++mi) {
        const int r0 = i0 + wm * 32 + mi * 16 + qr;
        #pragma unroll
        for (int ni = 0; ni < 4; ++ni) {
            const int c = j0 + wn * 32 + ni * 8 + qc * 2;
            float bx = bias[c], by = bias[c + 1];
            {
                long long off = (long long)r0 * HIDDEN + c;
                float2 v;
                v.x = acc[mi][ni][0] + bx;
                v.y = acc[mi][ni][1] + by;
                if (resid) { float2 rr = *(const float2*)&resid[off];
                             v.x += rr.x; v.y += rr.y; }
                *(float2*)&C[off] = v;
            }
            {
                long long off = (long long)(r0 + 8) * HIDDEN + c;
                float2 v;
                v.x = acc[mi][ni][2] + bx;
                v.y = acc[mi][ni][3] + by;
                if (resid) { float2 rr = *(const float2*)&resid[off];
                             v.x += rr.x; v.y += rr.y; }
                *(float2*)&C[off] = v;
            }
        }
    }
}

// ---------------------------------------------------------------------------
// Flash attention (tf32 MMA): grid (SEQ/128, B*H), 256 threads (8 warps).
// Each warp owns 16 full score rows (16x128) -> warp-local online softmax.
// Smem (dynamic, 171264 B):
//   Qs[128][68], Ks[128][68] : tf32 q/k tiles (K-contiguous, pad 4)
//   Vs[64][133]              : V transposed (d-major), pad 5 -> <=2-way reads
//   Ps[128][132]             : tf32 probabilities (pad 4)
// ---------------------------------------------------------------------------
#define FBQ  128
#define FBKV 128

#define QS_OFF 0
#define KS_OFF (128 * 68 * 4)                 // 34816
#define VS_OFF (KS_OFF + 128 * 68 * 4)        // 69632
#define PS_OFF (VS_OFF + 64 * 133 * 4)        // 103680
#define FLASH_SMEM (PS_OFF + 128 * 132 * 4)   // 171264

__global__ __launch_bounds__(256, 1) void flash_kernel(
    const float* __restrict__ Q, const float* __restrict__ K,
    const float* __restrict__ V, float* __restrict__ O)
{
    extern __shared__ char smem[];
    unsigned (*Qs)[68]  = (unsigned(*)[68]) (smem + QS_OFF);
    unsigned (*Ks)[68]  = (unsigned(*)[68]) (smem + KS_OFF);
    unsigned (*Vs)[133] = (unsigned(*)[133])(smem + VS_OFF);
    unsigned (*Ps)[132] = (unsigned(*)[132])(smem + PS_OFF);

    const int tid  = threadIdx.x;
    const int lane = tid & 31;
    const int wid  = tid >> 5;
    const int qr   = lane >> 2;
    const int qc   = lane & 3;
    const int z    = blockIdx.y;
    const int bb   = z >> 4;
    const int hh   = z & 15;
    const long long base = (long long)bb * SEQ * HIDDEN + hh * HEADD;
    const int q0 = blockIdx.x * FBQ;
    const int r0 = wid * 16;

    // ---- load Q tile (once): 128 rows x 64 cols = 2048 float4 ----
    #pragma unroll
    for (int it = 0; it < 8; ++it) {
        int idx = tid + it * 256;
        int row = idx >> 4;              // 16 float4 per 64-wide row
        int c4  = (idx & 15) * 4;
        float4 v = *(const float4*)(Q + base + (long long)(q0 + row) * HIDDEN + c4);
        *(uint4*)&Qs[row][c4] = make_uint4(f2tf(v.x), f2tf(v.y), f2tf(v.z), f2tf(v.w));
    }

    float accO[8][4];
    #pragma unroll
    for (int ni = 0; ni < 8; ++ni)
        #pragma unroll
        for (int r = 0; r < 4; ++r) accO[ni][r] = 0.0f;
    float m0 = -1e30f, m1 = -1e30f, l0 = 0.0f, l1 = 0.0f;

    for (int t = 0; t < SEQ / FBKV; ++t) {
        const int kv0 = t * FBKV;

        // ---- load K tile: full 128 rows ----
        #pragma unroll
        for (int it = 0; it < 8; ++it) {
            int idx = tid + it * 256;
            int row = idx >> 4;
            int c4  = (idx & 15) * 4;
            float4 v = *(const float4*)(K + base + (long long)(kv0 + row) * HIDDEN + c4);
            *(uint4*)&Ks[row][c4] = make_uint4(f2tf(v.x), f2tf(v.y), f2tf(v.z), f2tf(v.w));
        }
        // ---- load V tile transposed: Vs[d][kv] ----
        {
            int kvb = tid >> 4;          // 0..15
            int d4  = (tid & 15) * 4;
            #pragma unroll
            for (int it = 0; it < 8; ++it) {
                int kv = kvb + it * 16;
                float4 v = *(const float4*)(V + base + (long long)(kv0 + kv) * HIDDEN + d4);
                Vs[d4 + 0][kv] = f2tf(v.x);
                Vs[d4 + 1][kv] = f2tf(v.y);
                Vs[d4 + 2][kv] = f2tf(v.z);
                Vs[d4 + 3][kv] = f2tf(v.w);
            }
        }
        __syncthreads();

        // ---- S = Q @ K^T (warp: 16 rows x 128 cols) ----
        float accS[16][4];
        #pragma unroll
        for (int nt = 0; nt < 16; ++nt)
            #pragma unroll
            for (int r = 0; r < 4; ++r) accS[nt][r] = 0.0f;

        #pragma unroll
        for (int ks = 0; ks < 8; ++ks) {
            const int kb = ks * 8;
            unsigned a0 = Qs[r0 + qr][kb + qc];
            unsigned a1 = Qs[r0 + qr + 8][kb + qc];
            unsigned a2 = Qs[r0 + qr][kb + qc + 4];
            unsigned a3 = Qs[r0 + qr + 8][kb + qc + 4];
            #pragma unroll
            for (int nt = 0; nt < 16; ++nt) {
                unsigned b0 = Ks[nt * 8 + qr][kb + qc];
                unsigned b1 = Ks[nt * 8 + qr][kb + qc + 4];
                mma8(accS[nt], a0, a1, a2, a3, b0, b1);
            }
        }

        // ---- online softmax (rows qr and qr+8 of this warp) ----
        float rm0 = -1e30f, rm1 = -1e30f;
        #pragma unroll
        for (int nt = 0; nt < 16; ++nt) {
            accS[nt][0] *= 0.125f; accS[nt][1] *= 0.125f;
            accS[nt][2] *= 0.125f; accS[nt][3] *= 0.125f;
            rm0 = fmaxf(rm0, fmaxf(accS[nt][0], accS[nt][1]));
            rm1 = fmaxf(rm1, fmaxf(accS[nt][2], accS[nt][3]));
        }
        rm0 = fmaxf(rm0, __shfl_xor_sync(0xFFFFFFFFu, rm0, 1));
        rm0 = fmaxf(rm0, __shfl_xor_sync(0xFFFFFFFFu, rm0, 2));
        rm1 = fmaxf(rm1, __shfl_xor_sync(0xFFFFFFFFu, rm1, 1));
        rm1 = fmaxf(rm1, __shfl_xor_sync(0xFFFFFFFFu, rm1, 2));

        float nm0 = fmaxf(m0, rm0), nm1 = fmaxf(m1, rm1);
        float cr0 = __expf(m0 - nm0), cr1 = __expf(m1 - nm1);
        m0 = nm0; m1 = nm1;

        float s0 = 0.0f, s1 = 0.0f;
        #pragma unroll
        for (int nt = 0; nt < 16; ++nt) {
            unsigned p0 = f2tf(__expf(accS[nt][0] - m0));
            unsigned p1 = f2tf(__expf(accS[nt][1] - m0));
            unsigned p2 = f2tf(__expf(accS[nt][2] - m1));
            unsigned p3 = f2tf(__expf(accS[nt][3] - m1));
            s0 += __uint_as_float(p0) + __uint_as_float(p1);
            s1 += __uint_as_float(p2) + __uint_as_float(p3);
            int c = nt * 8 + 2 * qc;
            *(uint2*)&Ps[r0 + qr][c]     = make_uint2(p0, p1);
            *(uint2*)&Ps[r0 + qr + 8][c] = make_uint2(p2, p3);
        }
        s0 += __shfl_xor_sync(0xFFFFFFFFu, s0, 1);
        s0 += __shfl_xor_sync(0xFFFFFFFFu, s0, 2);
        s1 += __shfl_xor_sync(0xFFFFFFFFu, s1, 1);
        s1 += __shfl_xor_sync(0xFFFFFFFFu, s1, 2);
        l0 = l0 * cr0 + s0;
        l1 = l1 * cr1 + s1;

        #pragma unroll
        for (int ni = 0; ni < 8; ++ni) {
            accO[ni][0] *= cr0; accO[ni][1] *= cr0;
            accO[ni][2] *= cr1; accO[ni][3] *= cr1;
        }
        __syncwarp();

        // ---- O += P @ V ----
        #pragma unroll
        for (int ks = 0; ks < 16; ++ks) {
            const int kb = ks * 8;
            unsigned a0 = Ps[r0 + qr][kb + qc];
            unsigned a1 = Ps[r0 + qr + 8][kb + qc];
            unsigned a2 = Ps[r0 + qr][kb + qc + 4];
            unsigned a3 = Ps[r0 + qr + 8][kb + qc + 4];
            #pragma unroll
            for (int ni = 0; ni < 8; ++ni) {
                unsigned b0 = Vs[ni * 8 + qr][kb + qc];
                unsigned b1 = Vs[ni * 8 + qr][kb + qc + 4];
                mma8(accO[ni], a0, a1, a2, a3, b0, b1);
            }
        }
        __syncthreads();
    }

    // ---- epilogue: normalize, store ctx rows ----
    float i0 = 1.0f / l0, i1 = 1.0f / l1;
    #pragma unroll
    for (int ni = 0; ni < 8; ++ni) {
        int c = ni * 8 + 2 * qc;
        {
            long long off = base + (long long)(q0 + r0 + qr) * HIDDEN + c;
            float2 v; v.x = accO[ni][0] * i0; v.y = accO[ni][1] * i0;
            *(float2*)&O[off] = v;
        }
        {
            long long off = base + (long long)(q0 + r0 + qr + 8) * HIDDEN + c;
            float2 v; v.x = accO[ni][2] * i1; v.y = accO[ni][3] * i1;
            *(float2*)&O[off] = v;
        }
    }
}

// ---------------------------------------------------------------------------
// Launch
// ---------------------------------------------------------------------------
extern "C" void kernel_launch(void* const* d_in, const int* in_sizes, int n_in,
                              void* d_out, int out_size)
{
    (void)in_sizes; (void)n_in; (void)out_size;
    const float* x    = (const float*)d_in[0];
    const float* Wq   = (const float*)d_in[1];
    const float* bq   = (const float*)d_in[2];
    const float* Wk   = (const float*)d_in[3];
    const float* bk   = (const float*)d_in[4];
    const float* Wv   = (const float*)d_in[5];
    const float* bv   = (const float*)d_in[6];
    const float* Wo   = (const float*)d_in[7];
    const float* bo   = (const float*)d_in[8];
    const float* ln_g = (const float*)d_in[9];
    const float* ln_b = (const float*)d_in[10];
    float* out = (float*)d_out;

    float *xn, *q, *k, *v, *ctx;
    cudaGetSymbolAddress((void**)&xn,  g_xn);
    cudaGetSymbolAddress((void**)&q,   g_q);
    cudaGetSymbolAddress((void**)&k,   g_k);
    cudaGetSymbolAddress((void**)&v,   g_v);
    cudaGetSymbolAddress((void**)&ctx, g_ctx);

    cudaFuncSetAttribute(flash_kernel,
        cudaFuncAttributeMaxDynamicSharedMemorySize, FLASH_SMEM);

    // 1) LayerNorm
    ln_kernel<<<ROWS, 256>>>(x, ln_g, ln_b, xn);

    // 2) Q/K/V projections
    dim3 gProj(HIDDEN / TBN, ROWS / TBM, 1);
    gemm_tf32_kernel<<<gProj, 256>>>(xn, Wq, bq, nullptr, q, HIDDEN);
    gemm_tf32_kernel<<<gProj, 256>>>(xn, Wk, bk, nullptr, k, HIDDEN);
    gemm_tf32_kernel<<<gProj, 256>>>(xn, Wv, bv, nullptr, v, HIDDEN);

    // 3) fused attention -> ctx
    dim3 gFlash(SEQ / FBQ, BATCH * HEADS, 1);
    flash_kernel<<<gFlash, 256, FLASH_SMEM>>>(q, k, v, ctx);

    // 4) out = x + ctx @ Wo^T + bo
    gemm_tf32_kernel<<<gProj, 256>>>(ctx, Wo, bo, x, out, HIDDEN);
}

// round 7
// speedup vs baseline: 3.4252x; 1.1440x over previous
#include <cuda_runtime.h>
#include <cuda_bf16.h>

// ---------------------------------------------------------------------------
// MultiHeadAttention round 7:
//   LN -> fused QKV proj (tf32 MMA, cp.async double-buffered) ->
//   flash attention (unchanged from round 6) ->
//   out proj + bias + residual (same GEMM, z=1).
// GEMM changes vs round 6: 2-stage cp.async pipeline, raw-fp32-as-tf32
// (no cvt), QKV merged into one launch via gridDim.z.
// ---------------------------------------------------------------------------

#define HIDDEN 1024
#define SEQ    2048
#define BATCH  2
#define HEADS  16
#define HEADD  64
#define ROWS   (BATCH * SEQ)          // 4096

__device__ float g_xn [ROWS * HIDDEN];
__device__ float g_q  [ROWS * HIDDEN];
__device__ float g_k  [ROWS * HIDDEN];
__device__ float g_v  [ROWS * HIDDEN];
__device__ float g_ctx[ROWS * HIDDEN];

// ---------------------------------------------------------------------------
__device__ __forceinline__ unsigned f2tf(float f) {
    unsigned u;
    asm("cvt.rna.tf32.f32 %0, %1;" : "=r"(u) : "f"(f));
    return u;
}

__device__ __forceinline__ void mma8(float* c,
    unsigned a0, unsigned a1, unsigned a2, unsigned a3,
    unsigned b0, unsigned b1)
{
    asm volatile(
        "mma.sync.aligned.m16n8k8.row.col.f32.tf32.tf32.f32 "
        "{%0,%1,%2,%3},{%4,%5,%6,%7},{%8,%9},{%0,%1,%2,%3};"
        : "+f"(c[0]), "+f"(c[1]), "+f"(c[2]), "+f"(c[3])
        : "r"(a0), "r"(a1), "r"(a2), "r"(a3), "r"(b0), "r"(b1));
}

__device__ __forceinline__ void cp16(void* sp, const void* gp) {
    unsigned sa = (unsigned)__cvta_generic_to_shared(sp);
    asm volatile("cp.async.cg.shared.global [%0], [%1], 16;" :: "r"(sa), "l"(gp));
}
#define CP_COMMIT() asm volatile("cp.async.commit_group;")
#define CP_WAIT1()  asm volatile("cp.async.wait_group 1;")

__device__ __forceinline__ float blockReduceSum(float v, float* sh) {
    int lane = threadIdx.x & 31, w = threadIdx.x >> 5;
    #pragma unroll
    for (int o = 16; o; o >>= 1) v += __shfl_down_sync(0xFFFFFFFFu, v, o);
    if (lane == 0) sh[w] = v;
    __syncthreads();
    float r = 0.0f;
    if (w == 0) {
        r = (lane < (int)(blockDim.x >> 5)) ? sh[lane] : 0.0f;
        #pragma unroll
        for (int o = 16; o; o >>= 1) r += __shfl_down_sync(0xFFFFFFFFu, r, o);
        if (lane == 0) sh[0] = r;
    }
    __syncthreads();
    r = sh[0];
    __syncthreads();
    return r;
}

// ---------------------------------------------------------------------------
// LayerNorm: one block (256 threads) per row of 1024.
// ---------------------------------------------------------------------------
__global__ __launch_bounds__(256) void ln_kernel(
    const float* __restrict__ x, const float* __restrict__ g,
    const float* __restrict__ b, float* __restrict__ xn)
{
    __shared__ float sh[32];
    long long row = blockIdx.x;
    const float4 v = ((const float4*)(x + row * HIDDEN))[threadIdx.x];
    float s  = v.x + v.y + v.z + v.w;
    float sq = v.x*v.x + v.y*v.y + v.z*v.z + v.w*v.w;
    s  = blockReduceSum(s,  sh);
    sq = blockReduceSum(sq, sh);
    float mu  = s  * (1.0f / HIDDEN);
    float var = sq * (1.0f / HIDDEN) - mu * mu;
    float inv = rsqrtf(var + 1e-5f);
    float4 gg = ((const float4*)g)[threadIdx.x];
    float4 bb = ((const float4*)b)[threadIdx.x];
    float4 o;
    o.x = (v.x - mu) * inv * gg.x + bb.x;
    o.y = (v.y - mu) * inv * gg.y + bb.y;
    o.z = (v.z - mu) * inv * gg.z + bb.z;
    o.w = (v.w - mu) * inv * gg.w + bb.w;
    ((float4*)(xn + row * HIDDEN))[threadIdx.x] = o;
}

// ---------------------------------------------------------------------------
// tf32 tensor-core GEMM, 2-stage cp.async double buffer.
//   C[z] = A * W[z]^T + bias[z] (+resid), A[i,k]=A[i*1024+k], W row-major.
// Tile 128x64x32, 8 warps (4x2), warp tile 32x32. Raw fp32 bits fed as tf32.
// Dynamic smem: As[2][128][36] + Bs[2][64][36] u32 = 55296 B.
// ---------------------------------------------------------------------------
#define TBM 128
#define TBN 64
#define TBK 32
#define ASTR (TBK + 4)                       // 36
#define A_STG (TBM * ASTR)                   // 4608 u32
#define B_STG (TBN * ASTR)                   // 2304 u32
#define GEMM_SMEM ((2 * (A_STG + B_STG)) * 4)  // 55296 B

struct GemmPtrs {
    const float* W[3];
    const float* bias[3];
    float*       C[3];
};

__global__ __launch_bounds__(256) void gemm_tf32_db_kernel(
    const float* __restrict__ A, GemmPtrs p,
    const float* __restrict__ resid, int K)
{
    extern __shared__ unsigned gsm[];
    unsigned (*As)[TBM][ASTR] = (unsigned(*)[TBM][ASTR])gsm;
    unsigned (*Bs)[TBN][ASTR] = (unsigned(*)[TBN][ASTR])(gsm + 2 * A_STG);

    const int z = blockIdx.z;
    const float* __restrict__ B    = p.W[z];
    const float* __restrict__ bias = p.bias[z];
    float* __restrict__ C          = p.C[z];

    const int tid  = threadIdx.x;
    const int lane = tid & 31;
    const int wid  = tid >> 5;
    const int wm   = wid & 3;
    const int wn   = wid >> 2;
    const int qr   = lane >> 2;
    const int qc   = lane & 3;
    const int i0   = blockIdx.y * TBM;
    const int j0   = blockIdx.x * TBN;

    // per-thread load coords (one 16B cp.async each)
    const int la_r = tid >> 3;            // 0..31 (A: +32 per it, 4 its)
    const int la_k = (tid & 7) * 4;
    const int lb_r = tid >> 3;            // B: 2 its of 32 rows
    const int lb_k = (tid & 7) * 4;

    const int NT = K / TBK;

    // ---- prologue: stage 0 ----
    {
        const int k0 = 0;
        #pragma unroll
        for (int it = 0; it < 4; ++it)
            cp16(&As[0][la_r + it * 32][la_k],
                 A + (long long)(i0 + la_r + it * 32) * HIDDEN + (k0 + la_k));
        #pragma unroll
        for (int it = 0; it < 2; ++it)
            cp16(&Bs[0][lb_r + it * 32][lb_k],
                 B + (long long)(j0 + lb_r + it * 32) * HIDDEN + (k0 + lb_k));
        CP_COMMIT();
    }

    float acc[2][4][4];
    #pragma unroll
    for (int mi = 0; mi < 2; ++mi)
        #pragma unroll
        for (int ni = 0; ni < 4; ++ni)
            #pragma unroll
            for (int r = 0; r < 4; ++r) acc[mi][ni][r] = 0.0f;

    for (int t = 0; t < NT; ++t) {
        // issue next stage
        if (t + 1 < NT) {
            const int k0 = (t + 1) * TBK;
            const int s  = (t + 1) & 1;
            #pragma unroll
            for (int it = 0; it < 4; ++it)
                cp16(&As[s][la_r + it * 32][la_k],
                     A + (long long)(i0 + la_r + it * 32) * HIDDEN + (k0 + la_k));
            #pragma unroll
            for (int it = 0; it < 2; ++it)
                cp16(&Bs[s][lb_r + it * 32][lb_k],
                     B + (long long)(j0 + lb_r + it * 32) * HIDDEN + (k0 + lb_k));
        }
        CP_COMMIT();            // always commit (empty group on last iter)
        CP_WAIT1();             // stage t complete
        __syncthreads();

        const int s = t & 1;
        #pragma unroll
        for (int ks = 0; ks < 4; ++ks) {
            const int kb = ks * 8;
            unsigned a[2][4], b[4][2];
            #pragma unroll
            for (int mi = 0; mi < 2; ++mi) {
                int r = wm * 32 + mi * 16 + qr;
                a[mi][0] = As[s][r][kb + qc];
                a[mi][1] = As[s][r + 8][kb + qc];
                a[mi][2] = As[s][r][kb + qc + 4];
                a[mi][3] = As[s][r + 8][kb + qc + 4];
            }
            #pragma unroll
            for (int ni = 0; ni < 4; ++ni) {
                int c = wn * 32 + ni * 8 + qr;
                b[ni][0] = Bs[s][c][kb + qc];
                b[ni][1] = Bs[s][c][kb + qc + 4];
            }
            #pragma unroll
            for (int mi = 0; mi < 2; ++mi)
                #pragma unroll
                for (int ni = 0; ni < 4; ++ni)
                    mma8(acc[mi][ni], a[mi][0], a[mi][1], a[mi][2], a[mi][3],
                         b[ni][0], b[ni][1]);
        }
        __syncthreads();
    }

    #pragma unroll
    for (int mi = 0; mi < 2; ++mi) {
        const int r0 = i0 + wm * 32 + mi * 16 + qr;
        #pragma unroll
        for (int ni = 0; ni < 4; ++ni) {
            const int c = j0 + wn * 32 + ni * 8 + qc * 2;
            float bx = bias[c], by = bias[c + 1];
            {
                long long off = (long long)r0 * HIDDEN + c;
                float2 v;
                v.x = acc[mi][ni][0] + bx;
                v.y = acc[mi][ni][1] + by;
                if (resid) { float2 rr = *(const float2*)&resid[off];
                             v.x += rr.x; v.y += rr.y; }
                *(float2*)&C[off] = v;
            }
            {
                long long off = (long long)(r0 + 8) * HIDDEN + c;
                float2 v;
                v.x = acc[mi][ni][2] + bx;
                v.y = acc[mi][ni][3] + by;
                if (resid) { float2 rr = *(const float2*)&resid[off];
                             v.x += rr.x; v.y += rr.y; }
                *(float2*)&C[off] = v;
            }
        }
    }
}

// ---------------------------------------------------------------------------
// Flash attention (tf32 MMA): unchanged from round 6 (validated).
// ---------------------------------------------------------------------------
#define FBQ  128
#define FBKV 128

#define QS_OFF 0
#define KS_OFF (128 * 68 * 4)                 // 34816
#define VS_OFF (KS_OFF + 128 * 68 * 4)        // 69632
#define PS_OFF (VS_OFF + 64 * 133 * 4)        // 103680
#define FLASH_SMEM (PS_OFF + 128 * 132 * 4)   // 171264

__global__ __launch_bounds__(256, 1) void flash_kernel(
    const float* __restrict__ Q, const float* __restrict__ K,
    const float* __restrict__ V, float* __restrict__ O)
{
    extern __shared__ char smem[];
    unsigned (*Qs)[68]  = (unsigned(*)[68]) (smem + QS_OFF);
    unsigned (*Ks)[68]  = (unsigned(*)[68]) (smem + KS_OFF);
    unsigned (*Vs)[133] = (unsigned(*)[133])(smem + VS_OFF);
    unsigned (*Ps)[132] = (unsigned(*)[132])(smem + PS_OFF);

    const int tid  = threadIdx.x;
    const int lane = tid & 31;
    const int wid  = tid >> 5;
    const int qr   = lane >> 2;
    const int qc   = lane & 3;
    const int z    = blockIdx.y;
    const int bb   = z >> 4;
    const int hh   = z & 15;
    const long long base = (long long)bb * SEQ * HIDDEN + hh * HEADD;
    const int q0 = blockIdx.x * FBQ;
    const int r0 = wid * 16;

    // ---- load Q tile (once): 128 rows x 64 cols = 2048 float4 ----
    #pragma unroll
    for (int it = 0; it < 8; ++it) {
        int idx = tid + it * 256;
        int row = idx >> 4;
        int c4  = (idx & 15) * 4;
        float4 v = *(const float4*)(Q + base + (long long)(q0 + row) * HIDDEN + c4);
        *(uint4*)&Qs[row][c4] = make_uint4(f2tf(v.x), f2tf(v.y), f2tf(v.z), f2tf(v.w));
    }

    float accO[8][4];
    #pragma unroll
    for (int ni = 0; ni < 8; ++ni)
        #pragma unroll
        for (int r = 0; r < 4; ++r) accO[ni][r] = 0.0f;
    float m0 = -1e30f, m1 = -1e30f, l0 = 0.0f, l1 = 0.0f;

    for (int t = 0; t < SEQ / FBKV; ++t) {
        const int kv0 = t * FBKV;

        #pragma unroll
        for (int it = 0; it < 8; ++it) {
            int idx = tid + it * 256;
            int row = idx >> 4;
            int c4  = (idx & 15) * 4;
            float4 v = *(const float4*)(K + base + (long long)(kv0 + row) * HIDDEN + c4);
            *(uint4*)&Ks[row][c4] = make_uint4(f2tf(v.x), f2tf(v.y), f2tf(v.z), f2tf(v.w));
        }
        {
            int kvb = tid >> 4;
            int d4  = (tid & 15) * 4;
            #pragma unroll
            for (int it = 0; it < 8; ++it) {
                int kv = kvb + it * 16;
                float4 v = *(const float4*)(V + base + (long long)(kv0 + kv) * HIDDEN + d4);
                Vs[d4 + 0][kv] = f2tf(v.x);
                Vs[d4 + 1][kv] = f2tf(v.y);
                Vs[d4 + 2][kv] = f2tf(v.z);
                Vs[d4 + 3][kv] = f2tf(v.w);
            }
        }
        __syncthreads();

        float accS[16][4];
        #pragma unroll
        for (int nt = 0; nt < 16; ++nt)
            #pragma unroll
            for (int r = 0; r < 4; ++r) accS[nt][r] = 0.0f;

        #pragma unroll
        for (int ks = 0; ks < 8; ++ks) {
            const int kb = ks * 8;
            unsigned a0 = Qs[r0 + qr][kb + qc];
            unsigned a1 = Qs[r0 + qr + 8][kb + qc];
            unsigned a2 = Qs[r0 + qr][kb + qc + 4];
            unsigned a3 = Qs[r0 + qr + 8][kb + qc + 4];
            #pragma unroll
            for (int nt = 0; nt < 16; ++nt) {
                unsigned b0 = Ks[nt * 8 + qr][kb + qc];
                unsigned b1 = Ks[nt * 8 + qr][kb + qc + 4];
                mma8(accS[nt], a0, a1, a2, a3, b0, b1);
            }
        }

        float rm0 = -1e30f, rm1 = -1e30f;
        #pragma unroll
        for (int nt = 0; nt < 16; ++nt) {
            accS[nt][0] *= 0.125f; accS[nt][1] *= 0.125f;
            accS[nt][2] *= 0.125f; accS[nt][3] *= 0.125f;
            rm0 = fmaxf(rm0, fmaxf(accS[nt][0], accS[nt][1]));
            rm1 = fmaxf(rm1, fmaxf(accS[nt][2], accS[nt][3]));
        }
        rm0 = fmaxf(rm0, __shfl_xor_sync(0xFFFFFFFFu, rm0, 1));
        rm0 = fmaxf(rm0, __shfl_xor_sync(0xFFFFFFFFu, rm0, 2));
        rm1 = fmaxf(rm1, __shfl_xor_sync(0xFFFFFFFFu, rm1, 1));
        rm1 = fmaxf(rm1, __shfl_xor_sync(0xFFFFFFFFu, rm1, 2));

        float nm0 = fmaxf(m0, rm0), nm1 = fmaxf(m1, rm1);
        float cr0 = __expf(m0 - nm0), cr1 = __expf(m1 - nm1);
        m0 = nm0; m1 = nm1;

        float s0 = 0.0f, s1 = 0.0f;
        #pragma unroll
        for (int nt = 0; nt < 16; ++nt) {
            unsigned p0 = f2tf(__expf(accS[nt][0] - m0));
            unsigned p1 = f2tf(__expf(accS[nt][1] - m0));
            unsigned p2 = f2tf(__expf(accS[nt][2] - m1));
            unsigned p3 = f2tf(__expf(accS[nt][3] - m1));
            s0 += __uint_as_float(p0) + __uint_as_float(p1);
            s1 += __uint_as_float(p2) + __uint_as_float(p3);
            int c = nt * 8 + 2 * qc;
            *(uint2*)&Ps[r0 + qr][c]     = make_uint2(p0, p1);
            *(uint2*)&Ps[r0 + qr + 8][c] = make_uint2(p2, p3);
        }
        s0 += __shfl_xor_sync(0xFFFFFFFFu, s0, 1);
        s0 += __shfl_xor_sync(0xFFFFFFFFu, s0, 2);
        s1 += __shfl_xor_sync(0xFFFFFFFFu, s1, 1);
        s1 += __shfl_xor_sync(0xFFFFFFFFu, s1, 2);
        l0 = l0 * cr0 + s0;
        l1 = l1 * cr1 + s1;

        #pragma unroll
        for (int ni = 0; ni < 8; ++ni) {
            accO[ni][0] *= cr0; accO[ni][1] *= cr0;
            accO[ni][2] *= cr1; accO[ni][3] *= cr1;
        }
        __syncwarp();

        #pragma unroll
        for (int ks = 0; ks < 16; ++ks) {
            const int kb = ks * 8;
            unsigned a0 = Ps[r0 + qr][kb + qc];
            unsigned a1 = Ps[r0 + qr + 8][kb + qc];
            unsigned a2 = Ps[r0 + qr][kb + qc + 4];
            unsigned a3 = Ps[r0 + qr + 8][kb + qc + 4];
            #pragma unroll
            for (int ni = 0; ni < 8; ++ni) {
                unsigned b0 = Vs[ni * 8 + qr][kb + qc];
                unsigned b1 = Vs[ni * 8 + qr][kb + qc + 4];
                mma8(accO[ni], a0, a1, a2, a3, b0, b1);
            }
        }
        __syncthreads();
    }

    float i0 = 1.0f / l0, i1 = 1.0f / l1;
    #pragma unroll
    for (int ni = 0; ni < 8; ++ni) {
        int c = ni * 8 + 2 * qc;
        {
            long long off = base + (long long)(q0 + r0 + qr) * HIDDEN + c;
            float2 v; v.x = accO[ni][0] * i0; v.y = accO[ni][1] * i0;
            *(float2*)&O[off] = v;
        }
        {
            long long off = base + (long long)(q0 + r0 + qr + 8) * HIDDEN + c;
            float2 v; v.x = accO[ni][2] * i1; v.y = accO[ni][3] * i1;
            *(float2*)&O[off] = v;
        }
    }
}

// ---------------------------------------------------------------------------
// Launch
// ---------------------------------------------------------------------------
extern "C" void kernel_launch(void* const* d_in, const int* in_sizes, int n_in,
                              void* d_out, int out_size)
{
    (void)in_sizes; (void)n_in; (void)out_size;
    const float* x    = (const float*)d_in[0];
    const float* Wq   = (const float*)d_in[1];
    const float* bq   = (const float*)d_in[2];
    const float* Wk   = (const float*)d_in[3];
    const float* bk   = (const float*)d_in[4];
    const float* Wv   = (const float*)d_in[5];
    const float* bv   = (const float*)d_in[6];
    const float* Wo   = (const float*)d_in[7];
    const float* bo   = (const float*)d_in[8];
    const float* ln_g = (const float*)d_in[9];
    const float* ln_b = (const float*)d_in[10];
    float* out = (float*)d_out;

    float *xn, *q, *k, *v, *ctx;
    cudaGetSymbolAddress((void**)&xn,  g_xn);
    cudaGetSymbolAddress((void**)&q,   g_q);
    cudaGetSymbolAddress((void**)&k,   g_k);
    cudaGetSymbolAddress((void**)&v,   g_v);
    cudaGetSymbolAddress((void**)&ctx, g_ctx);

    cudaFuncSetAttribute(gemm_tf32_db_kernel,
        cudaFuncAttributeMaxDynamicSharedMemorySize, GEMM_SMEM);
    cudaFuncSetAttribute(flash_kernel,
        cudaFuncAttributeMaxDynamicSharedMemorySize, FLASH_SMEM);

    // 1) LayerNorm
    ln_kernel<<<ROWS, 256>>>(x, ln_g, ln_b, xn);

    // 2) fused Q/K/V projections (one launch, z selects weight set)
    GemmPtrs pq;
    pq.W[0] = Wq; pq.W[1] = Wk; pq.W[2] = Wv;
    pq.bias[0] = bq; pq.bias[1] = bk; pq.bias[2] = bv;
    pq.C[0] = q; pq.C[1] = k; pq.C[2] = v;
    dim3 gQKV(HIDDEN / TBN, ROWS / TBM, 3);
    gemm_tf32_db_kernel<<<gQKV, 256, GEMM_SMEM>>>(xn, pq, nullptr, HIDDEN);

    // 3) fused attention -> ctx
    dim3 gFlash(SEQ / FBQ, BATCH * HEADS, 1);
    flash_kernel<<<gFlash, 256, FLASH_SMEM>>>(q, k, v, ctx);

    // 4) out = x + ctx @ Wo^T + bo
    GemmPtrs po;
    po.W[0] = Wo; po.W[1] = Wo; po.W[2] = Wo;
    po.bias[0] = bo; po.bias[1] = bo; po.bias[2] = bo;
    po.C[0] = out; po.C[1] = out; po.C[2] = out;
    dim3 gOut(HIDDEN / TBN, ROWS / TBM, 1);
    gemm_tf32_db_kernel<<<gOut, 256, GEMM_SMEM>>>(ctx, po, x, HIDDEN);
}

// round 10
// speedup vs baseline: 3.4546x; 1.0086x over previous
#include <cuda_runtime.h>
#include <cuda_bf16.h>

// ---------------------------------------------------------------------------
// MultiHeadAttention round 10:
//   LN -> fused QKV proj (tf32 MMA, 128x128 tile, cp.async 2-stage) ->
//   flash attention (cp.async pipelined K/V, raw-fp32-as-tf32 loads) ->
//   out proj + bias + residual.
// Round-9 fix: flash cp.async tile loads were 4x undersized (512 of 2048
// 16B chunks; wrong row decomposition). Now 8 chunks/thread: row=c>>4,
// col=(c&15)*4. Ledger unchanged (incl. last-iter wait0).
// ---------------------------------------------------------------------------

#define HIDDEN 1024
#define SEQ    2048
#define BATCH  2
#define HEADS  16
#define HEADD  64
#define ROWS   (BATCH * SEQ)          // 4096

__device__ float g_xn [ROWS * HIDDEN];
__device__ float g_q  [ROWS * HIDDEN];
__device__ float g_k  [ROWS * HIDDEN];
__device__ float g_v  [ROWS * HIDDEN];
__device__ float g_ctx[ROWS * HIDDEN];

// ---------------------------------------------------------------------------
__device__ __forceinline__ unsigned f2tf(float f) {
    unsigned u;
    asm("cvt.rna.tf32.f32 %0, %1;" : "=r"(u) : "f"(f));
    return u;
}

__device__ __forceinline__ void mma8(float* c,
    unsigned a0, unsigned a1, unsigned a2, unsigned a3,
    unsigned b0, unsigned b1)
{
    asm volatile(
        "mma.sync.aligned.m16n8k8.row.col.f32.tf32.tf32.f32 "
        "{%0,%1,%2,%3},{%4,%5,%6,%7},{%8,%9},{%0,%1,%2,%3};"
        : "+f"(c[0]), "+f"(c[1]), "+f"(c[2]), "+f"(c[3])
        : "r"(a0), "r"(a1), "r"(a2), "r"(a3), "r"(b0), "r"(b1));
}

__device__ __forceinline__ void cp16(void* sp, const void* gp) {
    unsigned sa = (unsigned)__cvta_generic_to_shared(sp);
    asm volatile("cp.async.cg.shared.global [%0], [%1], 16;" :: "r"(sa), "l"(gp));
}
#define CP_COMMIT() asm volatile("cp.async.commit_group;")
#define CP_WAIT1()  asm volatile("cp.async.wait_group 1;")
#define CP_WAIT0()  asm volatile("cp.async.wait_group 0;")

__device__ __forceinline__ float blockReduceSum(float v, float* sh) {
    int lane = threadIdx.x & 31, w = threadIdx.x >> 5;
    #pragma unroll
    for (int o = 16; o; o >>= 1) v += __shfl_down_sync(0xFFFFFFFFu, v, o);
    if (lane == 0) sh[w] = v;
    __syncthreads();
    float r = 0.0f;
    if (w == 0) {
        r = (lane < (int)(blockDim.x >> 5)) ? sh[lane] : 0.0f;
        #pragma unroll
        for (int o = 16; o; o >>= 1) r += __shfl_down_sync(0xFFFFFFFFu, r, o);
        if (lane == 0) sh[0] = r;
    }
    __syncthreads();
    r = sh[0];
    __syncthreads();
    return r;
}

// ---------------------------------------------------------------------------
// LayerNorm: one block (256 threads) per row of 1024.
// ---------------------------------------------------------------------------
__global__ __launch_bounds__(256) void ln_kernel(
    const float* __restrict__ x, const float* __restrict__ g,
    const float* __restrict__ b, float* __restrict__ xn)
{
    __shared__ float sh[32];
    long long row = blockIdx.x;
    const float4 v = ((const float4*)(x + row * HIDDEN))[threadIdx.x];
    float s  = v.x + v.y + v.z + v.w;
    float sq = v.x*v.x + v.y*v.y + v.z*v.z + v.w*v.w;
    s  = blockReduceSum(s,  sh);
    sq = blockReduceSum(sq, sh);
    float mu  = s  * (1.0f / HIDDEN);
    float var = sq * (1.0f / HIDDEN) - mu * mu;
    float inv = rsqrtf(var + 1e-5f);
    float4 gg = ((const float4*)g)[threadIdx.x];
    float4 bb = ((const float4*)b)[threadIdx.x];
    float4 o;
    o.x = (v.x - mu) * inv * gg.x + bb.x;
    o.y = (v.y - mu) * inv * gg.y + bb.y;
    o.z = (v.z - mu) * inv * gg.z + bb.z;
    o.w = (v.w - mu) * inv * gg.w + bb.w;
    ((float4*)(xn + row * HIDDEN))[threadIdx.x] = o;
}

// ---------------------------------------------------------------------------
// tf32 GEMM, 128x128x32 tile, 2-stage cp.async double buffer.
//   C[z] = A * W[z]^T + bias[z] (+resid). Raw fp32 bits fed as tf32.
// 8 warps (4 M x 2 N), warp tile 32x64. Smem 73728 B dynamic.
// ---------------------------------------------------------------------------
#define TBM 128
#define TBN 128
#define TBK 32
#define ASTR (TBK + 4)                 // 36
#define A_STG (TBM * ASTR)             // 4608 u32
#define B_STG (TBN * ASTR)             // 4608 u32
#define GEMM_SMEM ((2 * (A_STG + B_STG)) * 4)   // 73728 B

struct GemmPtrs {
    const float* W[3];
    const float* bias[3];
    float*       C[3];
};

__global__ __launch_bounds__(256) void gemm_tf32_db_kernel(
    const float* __restrict__ A, GemmPtrs p,
    const float* __restrict__ resid, int K)
{
    extern __shared__ unsigned gsm[];
    unsigned (*As)[TBM][ASTR] = (unsigned(*)[TBM][ASTR])gsm;
    unsigned (*Bs)[TBN][ASTR] = (unsigned(*)[TBN][ASTR])(gsm + 2 * A_STG);

    const int z = blockIdx.z;
    const float* __restrict__ B    = p.W[z];
    const float* __restrict__ bias = p.bias[z];
    float* __restrict__ C          = p.C[z];

    const int tid  = threadIdx.x;
    const int lane = tid & 31;
    const int wid  = tid >> 5;
    const int wm   = wid & 3;          // 4 warps along M (32 rows each)
    const int wn   = wid >> 2;         // 2 warps along N (64 cols each)
    const int qr   = lane >> 2;
    const int qc   = lane & 3;
    const int i0   = blockIdx.y * TBM;
    const int j0   = blockIdx.x * TBN;

    const int l_r = tid >> 3;          // +32 per it (A/B tiles are 128x32: 8 chunks/row... 
    const int l_k = (tid & 7) * 4;     // 32 k-floats = 8 chunks of 4; 256 thr * 4 it = 1024 chunks = 128*8)

    const int NT = K / TBK;

    // ---- prologue: stage 0 ----
    #pragma unroll
    for (int it = 0; it < 4; ++it)
        cp16(&As[0][l_r + it * 32][l_k],
             A + (long long)(i0 + l_r + it * 32) * HIDDEN + l_k);
    #pragma unroll
    for (int it = 0; it < 4; ++it)
        cp16(&Bs[0][l_r + it * 32][l_k],
             B + (long long)(j0 + l_r + it * 32) * HIDDEN + l_k);
    CP_COMMIT();

    float acc[2][8][4];
    #pragma unroll
    for (int mi = 0; mi < 2; ++mi)
        #pragma unroll
        for (int ni = 0; ni < 8; ++ni)
            #pragma unroll
            for (int r = 0; r < 4; ++r) acc[mi][ni][r] = 0.0f;

    for (int t = 0; t < NT; ++t) {
        if (t + 1 < NT) {
            const int k0 = (t + 1) * TBK;
            const int s  = (t + 1) & 1;
            #pragma unroll
            for (int it = 0; it < 4; ++it)
                cp16(&As[s][l_r + it * 32][l_k],
                     A + (long long)(i0 + l_r + it * 32) * HIDDEN + (k0 + l_k));
            #pragma unroll
            for (int it = 0; it < 4; ++it)
                cp16(&Bs[s][l_r + it * 32][l_k],
                     B + (long long)(j0 + l_r + it * 32) * HIDDEN + (k0 + l_k));
        }
        CP_COMMIT();            // empty group on last iter keeps ledger uniform
        CP_WAIT1();
        __syncthreads();

        const int s = t & 1;
        #pragma unroll
        for (int ks = 0; ks < 4; ++ks) {
            const int kb = ks * 8;
            unsigned a[2][4], b[8][2];
            #pragma unroll
            for (int mi = 0; mi < 2; ++mi) {
                int r = wm * 32 + mi * 16 + qr;
                a[mi][0] = As[s][r][kb + qc];
                a[mi][1] = As[s][r + 8][kb + qc];
                a[mi][2] = As[s][r][kb + qc + 4];
                a[mi][3] = As[s][r + 8][kb + qc + 4];
            }
            #pragma unroll
            for (int ni = 0; ni < 8; ++ni) {
                int c = wn * 64 + ni * 8 + qr;
                b[ni][0] = Bs[s][c][kb + qc];
                b[ni][1] = Bs[s][c][kb + qc + 4];
            }
            #pragma unroll
            for (int mi = 0; mi < 2; ++mi)
                #pragma unroll
                for (int ni = 0; ni < 8; ++ni)
                    mma8(acc[mi][ni], a[mi][0], a[mi][1], a[mi][2], a[mi][3],
                         b[ni][0], b[ni][1]);
        }
        __syncthreads();
    }

    #pragma unroll
    for (int mi = 0; mi < 2; ++mi) {
        const int r0 = i0 + wm * 32 + mi * 16 + qr;
        #pragma unroll
        for (int ni = 0; ni < 8; ++ni) {
            const int c = j0 + wn * 64 + ni * 8 + qc * 2;
            float bx = bias[c], by = bias[c + 1];
            {
                long long off = (long long)r0 * HIDDEN + c;
                float2 v;
                v.x = acc[mi][ni][0] + bx;
                v.y = acc[mi][ni][1] + by;
                if (resid) { float2 rr = *(const float2*)&resid[off];
                             v.x += rr.x; v.y += rr.y; }
                *(float2*)&C[off] = v;
            }
            {
                long long off = (long long)(r0 + 8) * HIDDEN + c;
                float2 v;
                v.x = acc[mi][ni][2] + bx;
                v.y = acc[mi][ni][3] + by;
                if (resid) { float2 rr = *(const float2*)&resid[off];
                             v.x += rr.x; v.y += rr.y; }
                *(float2*)&C[off] = v;
            }
        }
    }
}

// ---------------------------------------------------------------------------
// Flash attention, cp.async pipelined.
// grid (SEQ/128, B*H), 256 threads (8 warps), each warp owns 16 score rows.
// Smem: Qs[128][68], Ks[128][68], Vr[128][68] (raw fp32; V row-major),
//       Ps[128][132] (tf32 probs). Total 172032 B.
// Tile load: 128 rows x 64 cols = 2048 x 16B chunks = 8 chunks/thread:
//   chunk c = tid + it*256, row = c>>4, col = (c&15)*4.
// Group ledger (commit order): Q, K0, V0, K1, V1, ..., K(NT-1), V(NT-1).
//   top-of-iter wait1  -> K(t) resident (V(t) may fly)
//   pre-PV: wait1 when K(t+1) group exists, else wait0 -> V(t) resident.
// ---------------------------------------------------------------------------
#define FBQ  128
#define FBKV 128

#define QS_OFF 0
#define KS_OFF (128 * 68 * 4)                 // 34816
#define VR_OFF (KS_OFF + 128 * 68 * 4)        // 69632
#define PS_OFF (VR_OFF + 128 * 68 * 4)        // 104448
#define FLASH_SMEM (PS_OFF + 128 * 132 * 4)   // 172032

__global__ __launch_bounds__(256, 1) void flash_kernel(
    const float* __restrict__ Q, const float* __restrict__ K,
    const float* __restrict__ V, float* __restrict__ O)
{
    extern __shared__ char smem[];
    unsigned (*Qs)[68]  = (unsigned(*)[68]) (smem + QS_OFF);
    unsigned (*Ks)[68]  = (unsigned(*)[68]) (smem + KS_OFF);
    unsigned (*Vr)[68]  = (unsigned(*)[68]) (smem + VR_OFF);
    unsigned (*Ps)[132] = (unsigned(*)[132])(smem + PS_OFF);

    const int tid  = threadIdx.x;
    const int lane = tid & 31;
    const int wid  = tid >> 5;
    const int qr   = lane >> 2;
    const int qc   = lane & 3;
    const int z    = blockIdx.y;
    const int bb   = z >> 4;
    const int hh   = z & 15;
    const long long base = (long long)bb * SEQ * HIDDEN + hh * HEADD;
    const int q0 = blockIdx.x * FBQ;
    const int r0 = wid * 16;

    // ---- prologue: Q, K0, V0 (three groups; 8 chunks/thread each) ----
    #pragma unroll
    for (int it = 0; it < 8; ++it) {
        int c = tid + it * 256;
        int r = c >> 4, cc = (c & 15) * 4;
        cp16(&Qs[r][cc], Q + base + (long long)(q0 + r) * HIDDEN + cc);
    }
    CP_COMMIT();
    #pragma unroll
    for (int it = 0; it < 8; ++it) {
        int c = tid + it * 256;
        int r = c >> 4, cc = (c & 15) * 4;
        cp16(&Ks[r][cc], K + base + (long long)r * HIDDEN + cc);
    }
    CP_COMMIT();
    #pragma unroll
    for (int it = 0; it < 8; ++it) {
        int c = tid + it * 256;
        int r = c >> 4, cc = (c & 15) * 4;
        cp16(&Vr[r][cc], V + base + (long long)r * HIDDEN + cc);
    }
    CP_COMMIT();

    float accO[8][4];
    #pragma unroll
    for (int ni = 0; ni < 8; ++ni)
        #pragma unroll
        for (int r = 0; r < 4; ++r) accO[ni][r] = 0.0f;
    float m0 = -1e30f, m1 = -1e30f, l0 = 0.0f, l1 = 0.0f;

    const int NT = SEQ / FBKV;
    for (int t = 0; t < NT; ++t) {
        CP_WAIT1();                 // Q + K(t) resident (V(t) may be in flight)
        __syncthreads();

        // ---- S = Q @ K^T (warp: 16 rows x 128 cols) ----
        float accS[16][4];
        #pragma unroll
        for (int nt = 0; nt < 16; ++nt)
            #pragma unroll
            for (int r = 0; r < 4; ++r) accS[nt][r] = 0.0f;

        #pragma unroll
        for (int ks = 0; ks < 8; ++ks) {
            const int kb = ks * 8;
            unsigned a0 = Qs[r0 + qr][kb + qc];
            unsigned a1 = Qs[r0 + qr + 8][kb + qc];
            unsigned a2 = Qs[r0 + qr][kb + qc + 4];
            unsigned a3 = Qs[r0 + qr + 8][kb + qc + 4];
            #pragma unroll
            for (int nt = 0; nt < 16; ++nt) {
                unsigned b0 = Ks[nt * 8 + qr][kb + qc];
                unsigned b1 = Ks[nt * 8 + qr][kb + qc + 4];
                mma8(accS[nt], a0, a1, a2, a3, b0, b1);
            }
        }
        __syncthreads();            // all warps done reading Ks

        // prefetch K(t+1) — overlaps softmax + PV below
        if (t + 1 < NT) {
            const long long kb2 = base + (long long)(t + 1) * FBKV * HIDDEN;
            #pragma unroll
            for (int it = 0; it < 8; ++it) {
                int c = tid + it * 256;
                int r = c >> 4, cc = (c & 15) * 4;
                cp16(&Ks[r][cc], K + kb2 + (long long)r * HIDDEN + cc);
            }
            CP_COMMIT();
        }

        // ---- online softmax (rows qr, qr+8 of this warp) ----
        float rm0 = -1e30f, rm1 = -1e30f;
        #pragma unroll
        for (int nt = 0; nt < 16; ++nt) {
            accS[nt][0] *= 0.125f; accS[nt][1] *= 0.125f;
            accS[nt][2] *= 0.125f; accS[nt][3] *= 0.125f;
            rm0 = fmaxf(rm0, fmaxf(accS[nt][0], accS[nt][1]));
            rm1 = fmaxf(rm1, fmaxf(accS[nt][2], accS[nt][3]));
        }
        rm0 = fmaxf(rm0, __shfl_xor_sync(0xFFFFFFFFu, rm0, 1));
        rm0 = fmaxf(rm0, __shfl_xor_sync(0xFFFFFFFFu, rm0, 2));
        rm1 = fmaxf(rm1, __shfl_xor_sync(0xFFFFFFFFu, rm1, 1));
        rm1 = fmaxf(rm1, __shfl_xor_sync(0xFFFFFFFFu, rm1, 2));

        float nm0 = fmaxf(m0, rm0), nm1 = fmaxf(m1, rm1);
        float cr_0 = __expf(m0 - nm0), cr_1 = __expf(m1 - nm1);
        m0 = nm0; m1 = nm1;

        float s0 = 0.0f, s1 = 0.0f;
        #pragma unroll
        for (int nt = 0; nt < 16; ++nt) {
            unsigned p0 = f2tf(__expf(accS[nt][0] - m0));
            unsigned p1 = f2tf(__expf(accS[nt][1] - m0));
            unsigned p2 = f2tf(__expf(accS[nt][2] - m1));
            unsigned p3 = f2tf(__expf(accS[nt][3] - m1));
            s0 += __uint_as_float(p0) + __uint_as_float(p1);
            s1 += __uint_as_float(p2) + __uint_as_float(p3);
            int c = nt * 8 + 2 * qc;
            *(uint2*)&Ps[r0 + qr][c]     = make_uint2(p0, p1);
            *(uint2*)&Ps[r0 + qr + 8][c] = make_uint2(p2, p3);
        }
        s0 += __shfl_xor_sync(0xFFFFFFFFu, s0, 1);
        s0 += __shfl_xor_sync(0xFFFFFFFFu, s0, 2);
        s1 += __shfl_xor_sync(0xFFFFFFFFu, s1, 1);
        s1 += __shfl_xor_sync(0xFFFFFFFFu, s1, 2);
        l0 = l0 * cr_0 + s0;
        l1 = l1 * cr_1 + s1;

        #pragma unroll
        for (int ni = 0; ni < 8; ++ni) {
            accO[ni][0] *= cr_0; accO[ni][1] *= cr_0;
            accO[ni][2] *= cr_1; accO[ni][3] *= cr_1;
        }
        __syncwarp();               // Ps rows visible within warp

        // V(t) must be resident. With a K(t+1) group committed, wait1 drains
        // through V(t); on the LAST iteration no such group exists -> wait0.
        if (t + 1 < NT) { CP_WAIT1(); } else { CP_WAIT0(); }
        __syncthreads();

        // ---- O += P @ V  (V row-major: B elem (kv,d) = Vr[kv][d]) ----
        #pragma unroll
        for (int ks = 0; ks < 16; ++ks) {
            const int kb = ks * 8;
            unsigned a0 = Ps[r0 + qr][kb + qc];
            unsigned a1 = Ps[r0 + qr + 8][kb + qc];
            unsigned a2 = Ps[r0 + qr][kb + qc + 4];
            unsigned a3 = Ps[r0 + qr + 8][kb + qc + 4];
            #pragma unroll
            for (int ni = 0; ni < 8; ++ni) {
                unsigned b0 = Vr[kb + qc][ni * 8 + qr];
                unsigned b1 = Vr[kb + qc + 4][ni * 8 + qr];
                mma8(accO[ni], a0, a1, a2, a3, b0, b1);
            }
        }
        __syncthreads();            // all warps done reading Vr

        // prefetch V(t+1) — overlaps QK of next iteration
        if (t + 1 < NT) {
            const long long vb2 = base + (long long)(t + 1) * FBKV * HIDDEN;
            #pragma unroll
            for (int it = 0; it < 8; ++it) {
                int c = tid + it * 256;
                int r = c >> 4, cc = (c & 15) * 4;
                cp16(&Vr[r][cc], V + vb2 + (long long)r * HIDDEN + cc);
            }
            CP_COMMIT();
        }
    }

    // ---- epilogue: normalize, store ctx rows ----
    float i0 = 1.0f / l0, i1 = 1.0f / l1;
    #pragma unroll
    for (int ni = 0; ni < 8; ++ni) {
        int c = ni * 8 + 2 * qc;
        {
            long long off = base + (long long)(q0 + r0 + qr) * HIDDEN + c;
            float2 v; v.x = accO[ni][0] * i0; v.y = accO[ni][1] * i0;
            *(float2*)&O[off] = v;
        }
        {
            long long off = base + (long long)(q0 + r0 + qr + 8) * HIDDEN + c;
            float2 v; v.x = accO[ni][2] * i1; v.y = accO[ni][3] * i1;
            *(float2*)&O[off] = v;
        }
    }
}

// ---------------------------------------------------------------------------
// Launch
// ---------------------------------------------------------------------------
extern "C" void kernel_launch(void* const* d_in, const int* in_sizes, int n_in,
                              void* d_out, int out_size)
{
    (void)in_sizes; (void)n_in; (void)out_size;
    const float* x    = (const float*)d_in[0];
    const float* Wq   = (const float*)d_in[1];
    const float* bq   = (const float*)d_in[2];
    const float* Wk   = (const float*)d_in[3];
    const float* bk   = (const float*)d_in[4];
    const float* Wv   = (const float*)d_in[5];
    const float* bv   = (const float*)d_in[6];
    const float* Wo   = (const float*)d_in[7];
    const float* bo   = (const float*)d_in[8];
    const float* ln_g = (const float*)d_in[9];
    const float* ln_b = (const float*)d_in[10];
    float* out = (float*)d_out;

    float *xn, *q, *k, *v, *ctx;
    cudaGetSymbolAddress((void**)&xn,  g_xn);
    cudaGetSymbolAddress((void**)&q,   g_q);
    cudaGetSymbolAddress((void**)&k,   g_k);
    cudaGetSymbolAddress((void**)&v,   g_v);
    cudaGetSymbolAddress((void**)&ctx, g_ctx);

    cudaFuncSetAttribute(gemm_tf32_db_kernel,
        cudaFuncAttributeMaxDynamicSharedMemorySize, GEMM_SMEM);
    cudaFuncSetAttribute(flash_kernel,
        cudaFuncAttributeMaxDynamicSharedMemorySize, FLASH_SMEM);

    // 1) LayerNorm
    ln_kernel<<<ROWS, 256>>>(x, ln_g, ln_b, xn);

    // 2) fused Q/K/V projections (one launch, z selects weight set)
    GemmPtrs pq;
    pq.W[0] = Wq; pq.W[1] = Wk; pq.W[2] = Wv;
    pq.bias[0] = bq; pq.bias[1] = bk; pq.bias[2] = bv;
    pq.C[0] = q; pq.C[1] = k; pq.C[2] = v;
    dim3 gQKV(HIDDEN / TBN, ROWS / TBM, 3);
    gemm_tf32_db_kernel<<<gQKV, 256, GEMM_SMEM>>>(xn, pq, nullptr, HIDDEN);

    // 3) fused attention -> ctx
    dim3 gFlash(SEQ / FBQ, BATCH * HEADS, 1);
    flash_kernel<<<gFlash, 256, FLASH_SMEM>>>(q, k, v, ctx);

    // 4) out = x + ctx @ Wo^T + bo
    GemmPtrs po;
    po.W[0] = Wo; po.W[1] = Wo; po.W[2] = Wo;
    po.bias[0] = bo; po.bias[1] = bo; po.bias[2] = bo;
    po.C[0] = out; po.C[1] = out; po.C[2] = out;
    dim3 gOut(HIDDEN / TBN, ROWS / TBM, 1);
    gemm_tf32_db_kernel<<<gOut, 256, GEMM_SMEM>>>(ctx, po, x, HIDDEN);
}

// round 11
// speedup vs baseline: 3.7274x; 1.0790x over previous
#include <cuda_runtime.h>
#include <cuda_bf16.h>

// ---------------------------------------------------------------------------
// MultiHeadAttention round 11:
//   LN -> fused QKV proj (tf32 MMA, 128x128, cp.async, 2 CTAs/SM) ->
//   flash attention (cp.async K/V, NO P round-trip: C-frag reused as A-frag
//   via kv-permuted V smem layout; 2 CTAs/SM) ->
//   out proj + bias + residual.
// ---------------------------------------------------------------------------

#define HIDDEN 1024
#define SEQ    2048
#define BATCH  2
#define HEADS  16
#define HEADD  64
#define ROWS   (BATCH * SEQ)          // 4096

__device__ float g_xn [ROWS * HIDDEN];
__device__ float g_q  [ROWS * HIDDEN];
__device__ float g_k  [ROWS * HIDDEN];
__device__ float g_v  [ROWS * HIDDEN];
__device__ float g_ctx[ROWS * HIDDEN];

// ---------------------------------------------------------------------------
__device__ __forceinline__ unsigned f2tf(float f) {
    unsigned u;
    asm("cvt.rna.tf32.f32 %0, %1;" : "=r"(u) : "f"(f));
    return u;
}

__device__ __forceinline__ void mma8(float* c,
    unsigned a0, unsigned a1, unsigned a2, unsigned a3,
    unsigned b0, unsigned b1)
{
    asm volatile(
        "mma.sync.aligned.m16n8k8.row.col.f32.tf32.tf32.f32 "
        "{%0,%1,%2,%3},{%4,%5,%6,%7},{%8,%9},{%0,%1,%2,%3};"
        : "+f"(c[0]), "+f"(c[1]), "+f"(c[2]), "+f"(c[3])
        : "r"(a0), "r"(a1), "r"(a2), "r"(a3), "r"(b0), "r"(b1));
}

__device__ __forceinline__ void cp16(void* sp, const void* gp) {
    unsigned sa = (unsigned)__cvta_generic_to_shared(sp);
    asm volatile("cp.async.cg.shared.global [%0], [%1], 16;" :: "r"(sa), "l"(gp));
}
#define CP_COMMIT() asm volatile("cp.async.commit_group;")
#define CP_WAIT1()  asm volatile("cp.async.wait_group 1;")
#define CP_WAIT0()  asm volatile("cp.async.wait_group 0;")

__device__ __forceinline__ float blockReduceSum(float v, float* sh) {
    int lane = threadIdx.x & 31, w = threadIdx.x >> 5;
    #pragma unroll
    for (int o = 16; o; o >>= 1) v += __shfl_down_sync(0xFFFFFFFFu, v, o);
    if (lane == 0) sh[w] = v;
    __syncthreads();
    float r = 0.0f;
    if (w == 0) {
        r = (lane < (int)(blockDim.x >> 5)) ? sh[lane] : 0.0f;
        #pragma unroll
        for (int o = 16; o; o >>= 1) r += __shfl_down_sync(0xFFFFFFFFu, r, o);
        if (lane == 0) sh[0] = r;
    }
    __syncthreads();
    r = sh[0];
    __syncthreads();
    return r;
}

// ---------------------------------------------------------------------------
// LayerNorm: one block (256 threads) per row of 1024.
// ---------------------------------------------------------------------------
__global__ __launch_bounds__(256) void ln_kernel(
    const float* __restrict__ x, const float* __restrict__ g,
    const float* __restrict__ b, float* __restrict__ xn)
{
    __shared__ float sh[32];
    long long row = blockIdx.x;
    const float4 v = ((const float4*)(x + row * HIDDEN))[threadIdx.x];
    float s  = v.x + v.y + v.z + v.w;
    float sq = v.x*v.x + v.y*v.y + v.z*v.z + v.w*v.w;
    s  = blockReduceSum(s,  sh);
    sq = blockReduceSum(sq, sh);
    float mu  = s  * (1.0f / HIDDEN);
    float var = sq * (1.0f / HIDDEN) - mu * mu;
    float inv = rsqrtf(var + 1e-5f);
    float4 gg = ((const float4*)g)[threadIdx.x];
    float4 bb = ((const float4*)b)[threadIdx.x];
    float4 o;
    o.x = (v.x - mu) * inv * gg.x + bb.x;
    o.y = (v.y - mu) * inv * gg.y + bb.y;
    o.z = (v.z - mu) * inv * gg.z + bb.z;
    o.w = (v.w - mu) * inv * gg.w + bb.w;
    ((float4*)(xn + row * HIDDEN))[threadIdx.x] = o;
}

// ---------------------------------------------------------------------------
// tf32 GEMM, 128x128x32 tile, 2-stage cp.async double buffer, 2 CTAs/SM.
// ---------------------------------------------------------------------------
#define TBM 128
#define TBN 128
#define TBK 32
#define ASTR (TBK + 4)                 // 36
#define A_STG (TBM * ASTR)             // 4608 u32
#define B_STG (TBN * ASTR)             // 4608 u32
#define GEMM_SMEM ((2 * (A_STG + B_STG)) * 4)   // 73728 B

struct GemmPtrs {
    const float* W[3];
    const float* bias[3];
    float*       C[3];
};

__global__ __launch_bounds__(256, 2) void gemm_tf32_db_kernel(
    const float* __restrict__ A, GemmPtrs p,
    const float* __restrict__ resid, int K)
{
    extern __shared__ unsigned gsm[];
    unsigned (*As)[TBM][ASTR] = (unsigned(*)[TBM][ASTR])gsm;
    unsigned (*Bs)[TBN][ASTR] = (unsigned(*)[TBN][ASTR])(gsm + 2 * A_STG);

    const int z = blockIdx.z;
    const float* __restrict__ B    = p.W[z];
    const float* __restrict__ bias = p.bias[z];
    float* __restrict__ C          = p.C[z];

    const int tid  = threadIdx.x;
    const int lane = tid & 31;
    const int wid  = tid >> 5;
    const int wm   = wid & 3;          // 4 warps along M (32 rows each)
    const int wn   = wid >> 2;         // 2 warps along N (64 cols each)
    const int qr   = lane >> 2;
    const int qc   = lane & 3;
    const int i0   = blockIdx.y * TBM;
    const int j0   = blockIdx.x * TBN;

    const int l_r = tid >> 3;          // 128x32 tile: 8 chunks/row, 4 its/thread
    const int l_k = (tid & 7) * 4;

    const int NT = K / TBK;

    // ---- prologue: stage 0 ----
    #pragma unroll
    for (int it = 0; it < 4; ++it)
        cp16(&As[0][l_r + it * 32][l_k],
             A + (long long)(i0 + l_r + it * 32) * HIDDEN + l_k);
    #pragma unroll
    for (int it = 0; it < 4; ++it)
        cp16(&Bs[0][l_r + it * 32][l_k],
             B + (long long)(j0 + l_r + it * 32) * HIDDEN + l_k);
    CP_COMMIT();

    float acc[2][8][4];
    #pragma unroll
    for (int mi = 0; mi < 2; ++mi)
        #pragma unroll
        for (int ni = 0; ni < 8; ++ni)
            #pragma unroll
            for (int r = 0; r < 4; ++r) acc[mi][ni][r] = 0.0f;

    for (int t = 0; t < NT; ++t) {
        if (t + 1 < NT) {
            const int k0 = (t + 1) * TBK;
            const int s  = (t + 1) & 1;
            #pragma unroll
            for (int it = 0; it < 4; ++it)
                cp16(&As[s][l_r + it * 32][l_k],
                     A + (long long)(i0 + l_r + it * 32) * HIDDEN + (k0 + l_k));
            #pragma unroll
            for (int it = 0; it < 4; ++it)
                cp16(&Bs[s][l_r + it * 32][l_k],
                     B + (long long)(j0 + l_r + it * 32) * HIDDEN + (k0 + l_k));
        }
        CP_COMMIT();            // empty group on last iter keeps ledger uniform
        CP_WAIT1();
        __syncthreads();

        const int s = t & 1;
        #pragma unroll
        for (int ks = 0; ks < 4; ++ks) {
            const int kb = ks * 8;
            unsigned a[2][4], b[8][2];
            #pragma unroll
            for (int mi = 0; mi < 2; ++mi) {
                int r = wm * 32 + mi * 16 + qr;
                a[mi][0] = As[s][r][kb + qc];
                a[mi][1] = As[s][r + 8][kb + qc];
                a[mi][2] = As[s][r][kb + qc + 4];
                a[mi][3] = As[s][r + 8][kb + qc + 4];
            }
            #pragma unroll
            for (int ni = 0; ni < 8; ++ni) {
                int c = wn * 64 + ni * 8 + qr;
                b[ni][0] = Bs[s][c][kb + qc];
                b[ni][1] = Bs[s][c][kb + qc + 4];
            }
            #pragma unroll
            for (int mi = 0; mi < 2; ++mi)
                #pragma unroll
                for (int ni = 0; ni < 8; ++ni)
                    mma8(acc[mi][ni], a[mi][0], a[mi][1], a[mi][2], a[mi][3],
                         b[ni][0], b[ni][1]);
        }
        __syncthreads();
    }

    #pragma unroll
    for (int mi = 0; mi < 2; ++mi) {
        const int r0 = i0 + wm * 32 + mi * 16 + qr;
        #pragma unroll
        for (int ni = 0; ni < 8; ++ni) {
            const int c = j0 + wn * 64 + ni * 8 + qc * 2;
            float bx = bias[c], by = bias[c + 1];
            {
                long long off = (long long)r0 * HIDDEN + c;
                float2 v;
                v.x = acc[mi][ni][0] + bx;
                v.y = acc[mi][ni][1] + by;
                if (resid) { float2 rr = *(const float2*)&resid[off];
                             v.x += rr.x; v.y += rr.y; }
                *(float2*)&C[off] = v;
            }
            {
                long long off = (long long)(r0 + 8) * HIDDEN + c;
                float2 v;
                v.x = acc[mi][ni][2] + bx;
                v.y = acc[mi][ni][3] + by;
                if (resid) { float2 rr = *(const float2*)&resid[off];
                             v.x += rr.x; v.y += rr.y; }
                *(float2*)&C[off] = v;
            }
        }
    }
}

// ---------------------------------------------------------------------------
// Flash attention, cp.async pipelined, NO P smem round-trip.
//
// Key trick: the m16n8k8 C-fragment (lane qr,qc holds cols {2qc,2qc+1} of
// rows {qr,qr+8}) becomes a valid A-fragment (k slots {qc,qc+4}) if the
// k (=kv) dimension of the next MMA is permuted: slot s<4 -> kv=2s,
// s>=4 -> kv=2s-7. So V rows are stored permuted in smem
// (logical r -> position (r&~7)|((r&7)>>1)|((r&1)<<2)), and the p-registers
// are passed as (c0, c2, c1, c3). PV b-frag indexing is then IDENTICAL to
// the unpermuted code: Vr[kb+qc][n], Vr[kb+qc+4][n].
//
// Smem: Qs/Ks/Vr [128][68] = 104448 B -> 2 CTAs/SM.
// Ledger: Q,K0,V0 then per iter K(t+1) after QK, V(t+1) after PV;
// waits: top wait1 (K(t)), pre-PV wait1 (or wait0 on last iter).
// ---------------------------------------------------------------------------
#define FBQ  128
#define FBKV 128

#define QS_OFF 0
#define KS_OFF (128 * 68 * 4)                 // 34816
#define VR_OFF (KS_OFF + 128 * 68 * 4)        // 69632
#define FLASH_SMEM (VR_OFF + 128 * 68 * 4)    // 104448

__global__ __launch_bounds__(256, 2) void flash_kernel(
    const float* __restrict__ Q, const float* __restrict__ K,
    const float* __restrict__ V, float* __restrict__ O)
{
    extern __shared__ char smem[];
    unsigned (*Qs)[68] = (unsigned(*)[68])(smem + QS_OFF);
    unsigned (*Ks)[68] = (unsigned(*)[68])(smem + KS_OFF);
    unsigned (*Vr)[68] = (unsigned(*)[68])(smem + VR_OFF);

    const int tid  = threadIdx.x;
    const int lane = tid & 31;
    const int wid  = tid >> 5;
    const int qr   = lane >> 2;
    const int qc   = lane & 3;
    const int z    = blockIdx.y;
    const int bb   = z >> 4;
    const int hh   = z & 15;
    const long long base = (long long)bb * SEQ * HIDDEN + hh * HEADD;
    const int q0 = blockIdx.x * FBQ;
    const int r0 = wid * 16;

    // ---- prologue: Q, K0, V0 (8 chunks/thread each; V rows permuted) ----
    #pragma unroll
    for (int it = 0; it < 8; ++it) {
        int c = tid + it * 256;
        int r = c >> 4, cc = (c & 15) * 4;
        cp16(&Qs[r][cc], Q + base + (long long)(q0 + r) * HIDDEN + cc);
    }
    CP_COMMIT();
    #pragma unroll
    for (int it = 0; it < 8; ++it) {
        int c = tid + it * 256;
        int r = c >> 4, cc = (c & 15) * 4;
        cp16(&Ks[r][cc], K + base + (long long)r * HIDDEN + cc);
    }
    CP_COMMIT();
    #pragma unroll
    for (int it = 0; it < 8; ++it) {
        int c = tid + it * 256;
        int r = c >> 4, cc = (c & 15) * 4;
        int pr = (r & ~7) | ((r & 7) >> 1) | ((r & 1) << 2);
        cp16(&Vr[pr][cc], V + base + (long long)r * HIDDEN + cc);
    }
    CP_COMMIT();

    float accO[8][4];
    #pragma unroll
    for (int ni = 0; ni < 8; ++ni)
        #pragma unroll
        for (int r = 0; r < 4; ++r) accO[ni][r] = 0.0f;
    float m0 = -1e30f, m1 = -1e30f, l0 = 0.0f, l1 = 0.0f;

    const int NT = SEQ / FBKV;
    for (int t = 0; t < NT; ++t) {
        CP_WAIT1();                 // Q + K(t) resident (V(t) may be in flight)
        __syncthreads();

        // ---- S = Q @ K^T (warp: 16 rows x 128 cols) ----
        float accS[16][4];
        #pragma unroll
        for (int nt = 0; nt < 16; ++nt)
            #pragma unroll
            for (int r = 0; r < 4; ++r) accS[nt][r] = 0.0f;

        #pragma unroll
        for (int ks = 0; ks < 8; ++ks) {
            const int kb = ks * 8;
            unsigned a0 = Qs[r0 + qr][kb + qc];
            unsigned a1 = Qs[r0 + qr + 8][kb + qc];
            unsigned a2 = Qs[r0 + qr][kb + qc + 4];
            unsigned a3 = Qs[r0 + qr + 8][kb + qc + 4];
            #pragma unroll
            for (int nt = 0; nt < 16; ++nt) {
                unsigned b0 = Ks[nt * 8 + qr][kb + qc];
                unsigned b1 = Ks[nt * 8 + qr][kb + qc + 4];
                mma8(accS[nt], a0, a1, a2, a3, b0, b1);
            }
        }
        __syncthreads();            // all warps done reading Ks

        // prefetch K(t+1) — overlaps softmax + PV below
        if (t + 1 < NT) {
            const long long kb2 = base + (long long)(t + 1) * FBKV * HIDDEN;
            #pragma unroll
            for (int it = 0; it < 8; ++it) {
                int c = tid + it * 256;
                int r = c >> 4, cc = (c & 15) * 4;
                cp16(&Ks[r][cc], K + kb2 + (long long)r * HIDDEN + cc);
            }
            CP_COMMIT();
        }

        // ---- online softmax (rows qr, qr+8 of this warp) ----
        float rm0 = -1e30f, rm1 = -1e30f;
        #pragma unroll
        for (int nt = 0; nt < 16; ++nt) {
            accS[nt][0] *= 0.125f; accS[nt][1] *= 0.125f;
            accS[nt][2] *= 0.125f; accS[nt][3] *= 0.125f;
            rm0 = fmaxf(rm0, fmaxf(accS[nt][0], accS[nt][1]));
            rm1 = fmaxf(rm1, fmaxf(accS[nt][2], accS[nt][3]));
        }
        rm0 = fmaxf(rm0, __shfl_xor_sync(0xFFFFFFFFu, rm0, 1));
        rm0 = fmaxf(rm0, __shfl_xor_sync(0xFFFFFFFFu, rm0, 2));
        rm1 = fmaxf(rm1, __shfl_xor_sync(0xFFFFFFFFu, rm1, 1));
        rm1 = fmaxf(rm1, __shfl_xor_sync(0xFFFFFFFFu, rm1, 2));

        float nm0 = fmaxf(m0, rm0), nm1 = fmaxf(m1, rm1);
        float cr_0 = __expf(m0 - nm0), cr_1 = __expf(m1 - nm1);
        m0 = nm0; m1 = nm1;

        // p = tf32(exp(s - m)) stored back into accS registers (bit pattern);
        // normalizer sums exactly the tf32-rounded values fed to the MMA.
        float s0 = 0.0f, s1 = 0.0f;
        #pragma unroll
        for (int nt = 0; nt < 16; ++nt) {
            unsigned p0 = f2tf(__expf(accS[nt][0] - m0));
            unsigned p1 = f2tf(__expf(accS[nt][1] - m0));
            unsigned p2 = f2tf(__expf(accS[nt][2] - m1));
            unsigned p3 = f2tf(__expf(accS[nt][3] - m1));
            s0 += __uint_as_float(p0) + __uint_as_float(p1);
            s1 += __uint_as_float(p2) + __uint_as_float(p3);
            accS[nt][0] = __uint_as_float(p0);
            accS[nt][1] = __uint_as_float(p1);
            accS[nt][2] = __uint_as_float(p2);
            accS[nt][3] = __uint_as_float(p3);
        }
        s0 += __shfl_xor_sync(0xFFFFFFFFu, s0, 1);
        s0 += __shfl_xor_sync(0xFFFFFFFFu, s0, 2);
        s1 += __shfl_xor_sync(0xFFFFFFFFu, s1, 1);
        s1 += __shfl_xor_sync(0xFFFFFFFFu, s1, 2);
        l0 = l0 * cr_0 + s0;
        l1 = l1 * cr_1 + s1;

        #pragma unroll
        for (int ni = 0; ni < 8; ++ni) {
            accO[ni][0] *= cr_0; accO[ni][1] *= cr_0;
            accO[ni][2] *= cr_1; accO[ni][3] *= cr_1;
        }

        // V(t) must be resident. With a K(t+1) group committed, wait1 drains
        // through V(t); on the LAST iteration no such group exists -> wait0.
        if (t + 1 < NT) { CP_WAIT1(); } else { CP_WAIT0(); }
        __syncthreads();

        // ---- O += P @ V. A-frag = reordered C-frag regs (c0,c2,c1,c3);
        //      V permutation makes b-frag indexing identical to unpermuted.
        #pragma unroll
        for (int nt = 0; nt < 16; ++nt) {
            const int kb = nt * 8;
            unsigned a0 = __float_as_uint(accS[nt][0]);   // (qr,  slot qc)
            unsigned a1 = __float_as_uint(accS[nt][2]);   // (qr+8,slot qc)
            unsigned a2 = __float_as_uint(accS[nt][1]);   // (qr,  slot qc+4)
            unsigned a3 = __float_as_uint(accS[nt][3]);   // (qr+8,slot qc+4)
            #pragma unroll
            for (int ni = 0; ni < 8; ++ni) {
                unsigned b0 = Vr[kb + qc][ni * 8 + qr];
                unsigned b1 = Vr[kb + qc + 4][ni * 8 + qr];
                mma8(accO[ni], a0, a1, a2, a3, b0, b1);
            }
        }
        __syncthreads();            // all warps done reading Vr

        // prefetch V(t+1) (permuted rows) — overlaps QK of next iteration
        if (t + 1 < NT) {
            const long long vb2 = base + (long long)(t + 1) * FBKV * HIDDEN;
            #pragma unroll
            for (int it = 0; it < 8; ++it) {
                int c = tid + it * 256;
                int r = c >> 4, cc = (c & 15) * 4;
                int pr = (r & ~7) | ((r & 7) >> 1) | ((r & 1) << 2);
                cp16(&Vr[pr][cc], V + vb2 + (long long)r * HIDDEN + cc);
            }
            CP_COMMIT();
        }
    }

    // ---- epilogue: normalize, store ctx rows ----
    float i0 = 1.0f / l0, i1 = 1.0f / l1;
    #pragma unroll
    for (int ni = 0; ni < 8; ++ni) {
        int c = ni * 8 + 2 * qc;
        {
            long long off = base + (long long)(q0 + r0 + qr) * HIDDEN + c;
            float2 v; v.x = accO[ni][0] * i0; v.y = accO[ni][1] * i0;
            *(float2*)&O[off] = v;
        }
        {
            long long off = base + (long long)(q0 + r0 + qr + 8) * HIDDEN + c;
            float2 v; v.x = accO[ni][2] * i1; v.y = accO[ni][3] * i1;
            *(float2*)&O[off] = v;
        }
    }
}

// ---------------------------------------------------------------------------
// Launch
// ---------------------------------------------------------------------------
extern "C" void kernel_launch(void* const* d_in, const int* in_sizes, int n_in,
                              void* d_out, int out_size)
{
    (void)in_sizes; (void)n_in; (void)out_size;
    const float* x    = (const float*)d_in[0];
    const float* Wq   = (const float*)d_in[1];
    const float* bq   = (const float*)d_in[2];
    const float* Wk   = (const float*)d_in[3];
    const float* bk   = (const float*)d_in[4];
    const float* Wv   = (const float*)d_in[5];
    const float* bv   = (const float*)d_in[6];
    const float* Wo   = (const float*)d_in[7];
    const float* bo   = (const float*)d_in[8];
    const float* ln_g = (const float*)d_in[9];
    const float* ln_b = (const float*)d_in[10];
    float* out = (float*)d_out;

    float *xn, *q, *k, *v, *ctx;
    cudaGetSymbolAddress((void**)&xn,  g_xn);
    cudaGetSymbolAddress((void**)&q,   g_q);
    cudaGetSymbolAddress((void**)&k,   g_k);
    cudaGetSymbolAddress((void**)&v,   g_v);
    cudaGetSymbolAddress((void**)&ctx, g_ctx);

    cudaFuncSetAttribute(gemm_tf32_db_kernel,
        cudaFuncAttributeMaxDynamicSharedMemorySize, GEMM_SMEM);
    cudaFuncSetAttribute(flash_kernel,
        cudaFuncAttributeMaxDynamicSharedMemorySize, FLASH_SMEM);

    // 1) LayerNorm
    ln_kernel<<<ROWS, 256>>>(x, ln_g, ln_b, xn);

    // 2) fused Q/K/V projections (one launch, z selects weight set)
    GemmPtrs pq;
    pq.W[0] = Wq; pq.W[1] = Wk; pq.W[2] = Wv;
    pq.bias[0] = bq; pq.bias[1] = bk; pq.bias[2] = bv;
    pq.C[0] = q; pq.C[1] = k; pq.C[2] = v;
    dim3 gQKV(HIDDEN / TBN, ROWS / TBM, 3);
    gemm_tf32_db_kernel<<<gQKV, 256, GEMM_SMEM>>>(xn, pq, nullptr, HIDDEN);

    // 3) fused attention -> ctx
    dim3 gFlash(SEQ / FBQ, BATCH * HEADS, 1);
    flash_kernel<<<gFlash, 256, FLASH_SMEM>>>(q, k, v, ctx);

    // 4) out = x + ctx @ Wo^T + bo
    GemmPtrs po;
    po.W[0] = Wo; po.W[1] = Wo; po.W[2] = Wo;
    po.bias[0] = bo; po.bias[1] = bo; po.bias[2] = bo;
    po.C[0] = out; po.C[1] = out; po.C[2] = out;
    dim3 gOut(HIDDEN / TBN, ROWS / TBM, 1);
    gemm_tf32_db_kernel<<<gOut, 256, GEMM_SMEM>>>(ctx, po, x, HIDDEN);
}

// round 12
// speedup vs baseline: 6.9339x; 1.8603x over previous
#include <cuda_runtime.h>
#include <cuda_bf16.h>

// ---------------------------------------------------------------------------
// MultiHeadAttention round 12 — bf16 end-to-end (m16n8k16):
//   convert W->bf16, LN->bf16 xn, fused QKV proj (bf16 MMA, cp.async),
//   vpair (V rows pre-paired for PV B-frags), flash attention (bf16, P in
//   registers, no smem round-trip), out proj fp32 epilogue + residual.
// ---------------------------------------------------------------------------

#define HIDDEN 1024
#define SEQ    2048
#define BATCH  2
#define HEADS  16
#define HEADD  64
#define ROWS   (BATCH * SEQ)          // 4096
#define HHALF  (HIDDEN / 2)           // 512 u32 per row of bf16

__device__ unsigned short g_xn [ROWS * HIDDEN];   // bf16
__device__ unsigned short g_q  [ROWS * HIDDEN];   // bf16
__device__ unsigned short g_k  [ROWS * HIDDEN];   // bf16
__device__ unsigned short g_v  [ROWS * HIDDEN];   // bf16
__device__ unsigned short g_ctx[ROWS * HIDDEN];   // bf16
__device__ unsigned       g_vp [BATCH * (SEQ/2) * HIDDEN]; // paired V, u32
__device__ unsigned short g_wq [HIDDEN * HIDDEN]; // bf16 weights
__device__ unsigned short g_wk [HIDDEN * HIDDEN];
__device__ unsigned short g_wv [HIDDEN * HIDDEN];
__device__ unsigned short g_wo [HIDDEN * HIDDEN];

// ---------------------------------------------------------------------------
__device__ __forceinline__ unsigned pack_bf16(float lo, float hi) {
    unsigned r;
    asm("cvt.rn.bf16x2.f32 %0, %1, %2;" : "=r"(r) : "f"(hi), "f"(lo));
    return r;   // lo -> lower half, hi -> upper half
}

__device__ __forceinline__ void mma16(float* c,
    unsigned a0, unsigned a1, unsigned a2, unsigned a3,
    unsigned b0, unsigned b1)
{
    asm volatile(
        "mma.sync.aligned.m16n8k16.row.col.f32.bf16.bf16.f32 "
        "{%0,%1,%2,%3},{%4,%5,%6,%7},{%8,%9},{%0,%1,%2,%3};"
        : "+f"(c[0]), "+f"(c[1]), "+f"(c[2]), "+f"(c[3])
        : "r"(a0), "r"(a1), "r"(a2), "r"(a3), "r"(b0), "r"(b1));
}

__device__ __forceinline__ void cp16(void* sp, const void* gp) {
    unsigned sa = (unsigned)__cvta_generic_to_shared(sp);
    asm volatile("cp.async.cg.shared.global [%0], [%1], 16;" :: "r"(sa), "l"(gp));
}
#define CP_COMMIT() asm volatile("cp.async.commit_group;")
#define CP_WAIT1()  asm volatile("cp.async.wait_group 1;")
#define CP_WAIT0()  asm volatile("cp.async.wait_group 0;")

__device__ __forceinline__ float blockReduceSum(float v, float* sh) {
    int lane = threadIdx.x & 31, w = threadIdx.x >> 5;
    #pragma unroll
    for (int o = 16; o; o >>= 1) v += __shfl_down_sync(0xFFFFFFFFu, v, o);
    if (lane == 0) sh[w] = v;
    __syncthreads();
    float r = 0.0f;
    if (w == 0) {
        r = (lane < (int)(blockDim.x >> 5)) ? sh[lane] : 0.0f;
        #pragma unroll
        for (int o = 16; o; o >>= 1) r += __shfl_down_sync(0xFFFFFFFFu, r, o);
        if (lane == 0) sh[0] = r;
    }
    __syncthreads();
    r = sh[0];
    __syncthreads();
    return r;
}

// ---------------------------------------------------------------------------
// Weight fp32 -> bf16 convert (1M elems per call).
// ---------------------------------------------------------------------------
__global__ __launch_bounds__(256) void convw_kernel(
    const float* __restrict__ src, unsigned* __restrict__ dst2)
{
    int id = blockIdx.x * 256 + threadIdx.x;          // 0 .. 262143
    float4 v = ((const float4*)src)[id];
    ((uint2*)dst2)[id] = make_uint2(pack_bf16(v.x, v.y), pack_bf16(v.z, v.w));
}

// ---------------------------------------------------------------------------
// LayerNorm: one block (256 threads) per row; outputs bf16.
// ---------------------------------------------------------------------------
__global__ __launch_bounds__(256) void ln_kernel(
    const float* __restrict__ x, const float* __restrict__ g,
    const float* __restrict__ b, unsigned* __restrict__ xn2)
{
    __shared__ float sh[32];
    long long row = blockIdx.x;
    const float4 v = ((const float4*)(x + row * HIDDEN))[threadIdx.x];
    float s  = v.x + v.y + v.z + v.w;
    float sq = v.x*v.x + v.y*v.y + v.z*v.z + v.w*v.w;
    s  = blockReduceSum(s,  sh);
    sq = blockReduceSum(sq, sh);
    float mu  = s  * (1.0f / HIDDEN);
    float var = sq * (1.0f / HIDDEN) - mu * mu;
    float inv = rsqrtf(var + 1e-5f);
    float4 gg = ((const float4*)g)[threadIdx.x];
    float4 bb = ((const float4*)b)[threadIdx.x];
    float ox = (v.x - mu) * inv * gg.x + bb.x;
    float oy = (v.y - mu) * inv * gg.y + bb.y;
    float oz = (v.z - mu) * inv * gg.z + bb.z;
    float ow = (v.w - mu) * inv * gg.w + bb.w;
    ((uint2*)(xn2 + row * HHALF))[threadIdx.x] =
        make_uint2(pack_bf16(ox, oy), pack_bf16(oz, ow));
}

// ---------------------------------------------------------------------------
// V pair kernel: vp[b*1024 + j][c] = {lo = v[b*2048+2j][c], hi = v[...2j+1][c]}
// One thread handles 4 consecutive columns.
// ---------------------------------------------------------------------------
__global__ __launch_bounds__(256) void vpair_kernel(
    const unsigned short* __restrict__ vbf, unsigned* __restrict__ vp)
{
    int id = blockIdx.x * 256 + threadIdx.x;          // 0 .. 524287
    int b  = id >> 18;                                 // /262144
    int jb = id & 262143;
    int j  = jb >> 8;
    int c0 = (jb & 255) * 4;
    const unsigned* ra = (const unsigned*)(vbf + ((long long)(b*SEQ + 2*j)     * HIDDEN) + c0);
    const unsigned* rb = (const unsigned*)(vbf + ((long long)(b*SEQ + 2*j + 1) * HIDDEN) + c0);
    uint2 a = *(const uint2*)ra;    // 4 halves from row 2j
    uint2 bq = *(const uint2*)rb;   // 4 halves from row 2j+1
    uint4 o;
    o.x = (a.x & 0xFFFFu) | (bq.x << 16);
    o.y = (a.x >> 16)     | (bq.x & 0xFFFF0000u);
    o.z = (a.y & 0xFFFFu) | (bq.y << 16);
    o.w = (a.y >> 16)     | (bq.y & 0xFFFF0000u);
    *(uint4*)(vp + ((long long)(b*1024 + j)) * HIDDEN + c0) = o;
}

// ---------------------------------------------------------------------------
// bf16 GEMM, 128x128x64 tile, 2-stage cp.async, 2 CTAs/SM.
//   C[z] = A * W[z]^T + bias[z]; OUT_FP32: fp32 C (+resid), else bf16 C.
// Smem u32 view: As/Bs [2][128][36] (64 halves + pad) = 73728 B.
// ---------------------------------------------------------------------------
#define TBM 128
#define TBN 128
#define TBKH 64                        // K halves per tile
#define GSTR 36                        // u32 stride (32 data + 4 pad)
#define G_STG (TBM * GSTR)             // 4608 u32
#define GEMM_SMEM ((4 * G_STG) * 4)    // 73728 B

struct GemmPtrs {
    const unsigned short* W[3];
    const float*          bias[3];
    void*                 C[3];
};

template<bool OUT_FP32>
__global__ __launch_bounds__(256, 2) void gemm_bf16_db_kernel(
    const unsigned short* __restrict__ A, GemmPtrs p,
    const float* __restrict__ resid)
{
    extern __shared__ unsigned gsm[];
    unsigned (*As)[TBM][GSTR] = (unsigned(*)[TBM][GSTR])gsm;
    unsigned (*Bs)[TBM][GSTR] = (unsigned(*)[TBM][GSTR])(gsm + 2 * G_STG);

    const int z = blockIdx.z;
    const unsigned short* __restrict__ B = p.W[z];
    const float* __restrict__ bias = p.bias[z];

    const int tid  = threadIdx.x;
    const int lane = tid & 31;
    const int wid  = tid >> 5;
    const int wm   = wid & 3;
    const int wn   = wid >> 2;
    const int qr   = lane >> 2;
    const int qc   = lane & 3;
    const int i0   = blockIdx.y * TBM;
    const int j0   = blockIdx.x * TBN;

    const int l_r = tid >> 3;          // 8 chunks/row (16B = 8 halves)
    const int l_h = (tid & 7) * 8;     // half offset in row
    const int l_u = (tid & 7) * 4;     // u32 offset in smem row

    const int NT = HIDDEN / TBKH;      // 16

    #pragma unroll
    for (int it = 0; it < 4; ++it)
        cp16(&As[0][l_r + it * 32][l_u],
             A + (long long)(i0 + l_r + it * 32) * HIDDEN + l_h);
    #pragma unroll
    for (int it = 0; it < 4; ++it)
        cp16(&Bs[0][l_r + it * 32][l_u],
             B + (long long)(j0 + l_r + it * 32) * HIDDEN + l_h);
    CP_COMMIT();

    float acc[2][8][4];
    #pragma unroll
    for (int mi = 0; mi < 2; ++mi)
        #pragma unroll
        for (int ni = 0; ni < 8; ++ni)
            #pragma unroll
            for (int r = 0; r < 4; ++r) acc[mi][ni][r] = 0.0f;

    for (int t = 0; t < NT; ++t) {
        if (t + 1 < NT) {
            const int k0 = (t + 1) * TBKH;
            const int s  = (t + 1) & 1;
            #pragma unroll
            for (int it = 0; it < 4; ++it)
                cp16(&As[s][l_r + it * 32][l_u],
                     A + (long long)(i0 + l_r + it * 32) * HIDDEN + (k0 + l_h));
            #pragma unroll
            for (int it = 0; it < 4; ++it)
                cp16(&Bs[s][l_r + it * 32][l_u],
                     B + (long long)(j0 + l_r + it * 32) * HIDDEN + (k0 + l_h));
        }
        CP_COMMIT();
        CP_WAIT1();
        __syncthreads();

        const int s = t & 1;
        #pragma unroll
        for (int ks = 0; ks < 4; ++ks) {           // 16 halves per kstep
            const int kb = ks * 8;                 // u32 offset
            unsigned a[2][4], b[8][2];
            #pragma unroll
            for (int mi = 0; mi < 2; ++mi) {
                int r = wm * 32 + mi * 16 + qr;
                a[mi][0] = As[s][r][kb + qc];
                a[mi][1] = As[s][r + 8][kb + qc];
                a[mi][2] = As[s][r][kb + qc + 4];
                a[mi][3] = As[s][r + 8][kb + qc + 4];
            }
            #pragma unroll
            for (int ni = 0; ni < 8; ++ni) {
                int c = wn * 64 + ni * 8 + qr;
                b[ni][0] = Bs[s][c][kb + qc];
                b[ni][1] = Bs[s][c][kb + qc + 4];
            }
            #pragma unroll
            for (int mi = 0; mi < 2; ++mi)
                #pragma unroll
                for (int ni = 0; ni < 8; ++ni)
                    mma16(acc[mi][ni], a[mi][0], a[mi][1], a[mi][2], a[mi][3],
                          b[ni][0], b[ni][1]);
        }
        __syncthreads();
    }

    #pragma unroll
    for (int mi = 0; mi < 2; ++mi) {
        const int r0 = i0 + wm * 32 + mi * 16 + qr;
        #pragma unroll
        for (int ni = 0; ni < 8; ++ni) {
            const int c = j0 + wn * 64 + ni * 8 + qc * 2;
            float bx = bias[c], by = bias[c + 1];
            if (OUT_FP32) {
                float* C = (float*)p.C[z];
                {
                    long long off = (long long)r0 * HIDDEN + c;
                    float2 v;
                    v.x = acc[mi][ni][0] + bx;
                    v.y = acc[mi][ni][1] + by;
                    if (resid) { float2 rr = *(const float2*)&resid[off];
                                 v.x += rr.x; v.y += rr.y; }
                    *(float2*)&C[off] = v;
                }
                {
                    long long off = (long long)(r0 + 8) * HIDDEN + c;
                    float2 v;
                    v.x = acc[mi][ni][2] + bx;
                    v.y = acc[mi][ni][3] + by;
                    if (resid) { float2 rr = *(const float2*)&resid[off];
                                 v.x += rr.x; v.y += rr.y; }
                    *(float2*)&C[off] = v;
                }
            } else {
                unsigned* C = (unsigned*)p.C[z];
                const int cu = c >> 1;
                C[(long long)r0 * HHALF + cu] =
                    pack_bf16(acc[mi][ni][0] + bx, acc[mi][ni][1] + by);
                C[(long long)(r0 + 8) * HHALF + cu] =
                    pack_bf16(acc[mi][ni][2] + bx, acc[mi][ni][3] + by);
            }
        }
    }
}

// ---------------------------------------------------------------------------
// Flash attention, bf16 m16n8k16, cp.async pipelined, P in registers.
// Smem (u32 view): Qs[128][36], Ks[128][36] (64 halves + pad),
//                  Vp[64][68]  (paired V: 64 u32 data + 4 pad)  = 54272 B.
// QK: 4 ksteps x 16 nt. PV: 8 ksteps x 8 ni; A-frags = bf16-packed score
// C-frags (a0=pack(c0,c1)[2ks], a1=pack(c2,c3)[2ks], a2/a3 from tile 2ks+1);
// B-frags = scalar LDS from paired V. Ledger as rounds 10/11.
// ---------------------------------------------------------------------------
#define FBQ  128
#define FBKV 128

#define QS_U 0
#define KS_U (128 * 36)                       // u32 offsets
#define VP_U (KS_U + 128 * 36)
#define FLASH_SMEM ((VP_U + 64 * 68) * 4)     // 54272 B

__global__ __launch_bounds__(256, 2) void flash_kernel(
    const unsigned short* __restrict__ Q, const unsigned short* __restrict__ K,
    const unsigned* __restrict__ VP, unsigned* __restrict__ Obf)
{
    extern __shared__ unsigned fsm[];
    unsigned (*Qs)[36] = (unsigned(*)[36])(fsm + QS_U);
    unsigned (*Ks)[36] = (unsigned(*)[36])(fsm + KS_U);
    unsigned (*Vp)[68] = (unsigned(*)[68])(fsm + VP_U);

    const int tid  = threadIdx.x;
    const int lane = tid & 31;
    const int wid  = tid >> 5;
    const int qr   = lane >> 2;
    const int qc   = lane & 3;
    const int z    = blockIdx.y;
    const int bb   = z >> 4;
    const int hh   = z & 15;
    const long long baseH = (long long)bb * SEQ * HIDDEN + hh * HEADD;   // halves
    const int q0 = blockIdx.x * FBQ;
    const int r0 = wid * 16;

    // Q/K tiles: 128 rows x 8 chunks = 1024 -> 4 chunks/thread
    // Vp tile:    64 rows x 16 chunks = 1024 -> 4 chunks/thread
    #pragma unroll
    for (int it = 0; it < 4; ++it) {
        int c = tid + it * 256;
        int r = c >> 3, ch = c & 7;
        cp16(&Qs[r][ch * 4], Q + baseH + (long long)(q0 + r) * HIDDEN + ch * 8);
    }
    CP_COMMIT();
    #pragma unroll
    for (int it = 0; it < 4; ++it) {
        int c = tid + it * 256;
        int r = c >> 3, ch = c & 7;
        cp16(&Ks[r][ch * 4], K + baseH + (long long)r * HIDDEN + ch * 8);
    }
    CP_COMMIT();
    {
        const long long vpb = ((long long)bb * 1024) * HIDDEN + hh * HEADD;
        #pragma unroll
        for (int it = 0; it < 4; ++it) {
            int c = tid + it * 256;
            int r = c >> 4, ch = c & 15;
            cp16(&Vp[r][ch * 4], VP + vpb + (long long)r * HIDDEN + ch * 4);
        }
    }
    CP_COMMIT();

    float accO[8][4];
    #pragma unroll
    for (int ni = 0; ni < 8; ++ni)
        #pragma unroll
        for (int r = 0; r < 4; ++r) accO[ni][r] = 0.0f;
    float m0 = -1e30f, m1 = -1e30f, l0 = 0.0f, l1 = 0.0f;

    const int NT = SEQ / FBKV;
    for (int t = 0; t < NT; ++t) {
        CP_WAIT1();                 // Q + K(t) resident
        __syncthreads();

        // ---- S = Q @ K^T : 4 ksteps (k=16 each) x 16 col-tiles ----
        float accS[16][4];
        #pragma unroll
        for (int nt = 0; nt < 16; ++nt)
            #pragma unroll
            for (int r = 0; r < 4; ++r) accS[nt][r] = 0.0f;

        #pragma unroll
        for (int ks = 0; ks < 4; ++ks) {
            const int kb = ks * 8;
            unsigned a0 = Qs[r0 + qr][kb + qc];
            unsigned a1 = Qs[r0 + qr + 8][kb + qc];
            unsigned a2 = Qs[r0 + qr][kb + qc + 4];
            unsigned a3 = Qs[r0 + qr + 8][kb + qc + 4];
            #pragma unroll
            for (int nt = 0; nt < 16; ++nt) {
                unsigned b0 = Ks[nt * 8 + qr][kb + qc];
                unsigned b1 = Ks[nt * 8 + qr][kb + qc + 4];
                mma16(accS[nt], a0, a1, a2, a3, b0, b1);
            }
        }
        __syncthreads();            // all warps done reading Ks

        // prefetch K(t+1)
        if (t + 1 < NT) {
            const long long kb2 = baseH + (long long)(t + 1) * FBKV * HIDDEN;
            #pragma unroll
            for (int it = 0; it < 4; ++it) {
                int c = tid + it * 256;
                int r = c >> 3, ch = c & 7;
                cp16(&Ks[r][ch * 4], K + kb2 + (long long)r * HIDDEN + ch * 8);
            }
            CP_COMMIT();
        }

        // ---- online softmax ----
        float rm0 = -1e30f, rm1 = -1e30f;
        #pragma unroll
        for (int nt = 0; nt < 16; ++nt) {
            accS[nt][0] *= 0.125f; accS[nt][1] *= 0.125f;
            accS[nt][2] *= 0.125f; accS[nt][3] *= 0.125f;
            rm0 = fmaxf(rm0, fmaxf(accS[nt][0], accS[nt][1]));
            rm1 = fmaxf(rm1, fmaxf(accS[nt][2], accS[nt][3]));
        }
        rm0 = fmaxf(rm0, __shfl_xor_sync(0xFFFFFFFFu, rm0, 1));
        rm0 = fmaxf(rm0, __shfl_xor_sync(0xFFFFFFFFu, rm0, 2));
        rm1 = fmaxf(rm1, __shfl_xor_sync(0xFFFFFFFFu, rm1, 1));
        rm1 = fmaxf(rm1, __shfl_xor_sync(0xFFFFFFFFu, rm1, 2));

        float nm0 = fmaxf(m0, rm0), nm1 = fmaxf(m1, rm1);
        float cr_0 = __expf(m0 - nm0), cr_1 = __expf(m1 - nm1);
        m0 = nm0; m1 = nm1;

        // p = bf16(exp(s-m)); pack pairs into accS[nt][0] (rows qr) and
        // accS[nt][1] (rows qr+8); normalizer sums the rounded values.
        float s0 = 0.0f, s1 = 0.0f;
        #pragma unroll
        for (int nt = 0; nt < 16; ++nt) {
            float p0 = __expf(accS[nt][0] - m0);
            float p1 = __expf(accS[nt][1] - m0);
            float p2 = __expf(accS[nt][2] - m1);
            float p3 = __expf(accS[nt][3] - m1);
            unsigned p01 = pack_bf16(p0, p1);
            unsigned p23 = pack_bf16(p2, p3);
            s0 += __uint_as_float(p01 << 16) + __uint_as_float(p01 & 0xFFFF0000u);
            s1 += __uint_as_float(p23 << 16) + __uint_as_float(p23 & 0xFFFF0000u);
            accS[nt][0] = __uint_as_float(p01);
            accS[nt][1] = __uint_as_float(p23);
        }
        s0 += __shfl_xor_sync(0xFFFFFFFFu, s0, 1);
        s0 += __shfl_xor_sync(0xFFFFFFFFu, s0, 2);
        s1 += __shfl_xor_sync(0xFFFFFFFFu, s1, 1);
        s1 += __shfl_xor_sync(0xFFFFFFFFu, s1, 2);
        l0 = l0 * cr_0 + s0;
        l1 = l1 * cr_1 + s1;

        #pragma unroll
        for (int ni = 0; ni < 8; ++ni) {
            accO[ni][0] *= cr_0; accO[ni][1] *= cr_0;
            accO[ni][2] *= cr_1; accO[ni][3] *= cr_1;
        }

        if (t + 1 < NT) { CP_WAIT1(); } else { CP_WAIT0(); }   // V(t) resident
        __syncthreads();

        // ---- O += P @ V : 8 ksteps (kv=16 each) x 8 d-tiles ----
        #pragma unroll
        for (int ks = 0; ks < 8; ++ks) {
            unsigned a0 = __float_as_uint(accS[2*ks][0]);     // rows qr,  kv 2qc..
            unsigned a1 = __float_as_uint(accS[2*ks][1]);     // rows qr+8
            unsigned a2 = __float_as_uint(accS[2*ks+1][0]);   // kv 2qc+8..
            unsigned a3 = __float_as_uint(accS[2*ks+1][1]);
            #pragma unroll
            for (int ni = 0; ni < 8; ++ni) {
                unsigned b0 = Vp[8*ks + qc][ni * 8 + qr];
                unsigned b1 = Vp[8*ks + qc + 4][ni * 8 + qr];
                mma16(accO[ni], a0, a1, a2, a3, b0, b1);
            }
        }
        __syncthreads();            // all warps done reading Vp

        // prefetch V(t+1) pairs
        if (t + 1 < NT) {
            const long long vpb = ((long long)bb * 1024 + (long long)(t + 1) * 64)
                                  * HIDDEN + hh * HEADD;
            #pragma unroll
            for (int it = 0; it < 4; ++it) {
                int c = tid + it * 256;
                int r = c >> 4, ch = c & 15;
                cp16(&Vp[r][ch * 4], VP + vpb + (long long)r * HIDDEN + ch * 4);
            }
            CP_COMMIT();
        }
    }

    // ---- epilogue: normalize, store ctx (bf16) ----
    float i0 = 1.0f / l0, i1 = 1.0f / l1;
    const long long obase = ((long long)bb * SEQ) * HHALF + hh * (HEADD / 2);
    #pragma unroll
    for (int ni = 0; ni < 8; ++ni) {
        int cu = ni * 4 + qc;       // u32 col within head (pairs 2qc,2qc+1)
        Obf[obase + (long long)(q0 + r0 + qr) * HHALF + cu] =
            pack_bf16(accO[ni][0] * i0, accO[ni][1] * i0);
        Obf[obase + (long long)(q0 + r0 + qr + 8) * HHALF + cu] =
            pack_bf16(accO[ni][2] * i1, accO[ni][3] * i1);
    }
}

// ---------------------------------------------------------------------------
// Launch
// ---------------------------------------------------------------------------
extern "C" void kernel_launch(void* const* d_in, const int* in_sizes, int n_in,
                              void* d_out, int out_size)
{
    (void)in_sizes; (void)n_in; (void)out_size;
    const float* x    = (const float*)d_in[0];
    const float* Wq   = (const float*)d_in[1];
    const float* bq   = (const float*)d_in[2];
    const float* Wk   = (const float*)d_in[3];
    const float* bk   = (const float*)d_in[4];
    const float* Wv   = (const float*)d_in[5];
    const float* bv   = (const float*)d_in[6];
    const float* Wo   = (const float*)d_in[7];
    const float* bo   = (const float*)d_in[8];
    const float* ln_g = (const float*)d_in[9];
    const float* ln_b = (const float*)d_in[10];
    float* out = (float*)d_out;

    unsigned short *xn, *q, *k, *v, *ctx, *wq, *wk, *wv, *wo;
    unsigned *vp;
    cudaGetSymbolAddress((void**)&xn,  g_xn);
    cudaGetSymbolAddress((void**)&q,   g_q);
    cudaGetSymbolAddress((void**)&k,   g_k);
    cudaGetSymbolAddress((void**)&v,   g_v);
    cudaGetSymbolAddress((void**)&ctx, g_ctx);
    cudaGetSymbolAddress((void**)&vp,  g_vp);
    cudaGetSymbolAddress((void**)&wq,  g_wq);
    cudaGetSymbolAddress((void**)&wk,  g_wk);
    cudaGetSymbolAddress((void**)&wv,  g_wv);
    cudaGetSymbolAddress((void**)&wo,  g_wo);

    cudaFuncSetAttribute(gemm_bf16_db_kernel<false>,
        cudaFuncAttributeMaxDynamicSharedMemorySize, GEMM_SMEM);
    cudaFuncSetAttribute(gemm_bf16_db_kernel<true>,
        cudaFuncAttributeMaxDynamicSharedMemorySize, GEMM_SMEM);
    cudaFuncSetAttribute(flash_kernel,
        cudaFuncAttributeMaxDynamicSharedMemorySize, FLASH_SMEM);

    // 0) weights -> bf16
    convw_kernel<<<1024, 256>>>(Wq, (unsigned*)wq);
    convw_kernel<<<1024, 256>>>(Wk, (unsigned*)wk);
    convw_kernel<<<1024, 256>>>(Wv, (unsigned*)wv);
    convw_kernel<<<1024, 256>>>(Wo, (unsigned*)wo);

    // 1) LayerNorm (bf16 out)
    ln_kernel<<<ROWS, 256>>>(x, ln_g, ln_b, (unsigned*)xn);

    // 2) fused Q/K/V projections (bf16 out)
    GemmPtrs pq;
    pq.W[0] = wq; pq.W[1] = wk; pq.W[2] = wv;
    pq.bias[0] = bq; pq.bias[1] = bk; pq.bias[2] = bv;
    pq.C[0] = q; pq.C[1] = k; pq.C[2] = v;
    dim3 gQKV(HIDDEN / TBN, ROWS / TBM, 3);
    gemm_bf16_db_kernel<false><<<gQKV, 256, GEMM_SMEM>>>(xn, pq, nullptr);

    // 3) pair V rows for PV B-fragments
    vpair_kernel<<<2048, 256>>>(v, vp);

    // 4) flash attention -> ctx (bf16)
    dim3 gFlash(SEQ / FBQ, BATCH * HEADS, 1);
    flash_kernel<<<gFlash, 256, FLASH_SMEM>>>(q, k, vp, (unsigned*)ctx);

    // 5) out = x + ctx @ Wo^T + bo (fp32)
    GemmPtrs po;
    po.W[0] = wo; po.W[1] = wo; po.W[2] = wo;
    po.bias[0] = bo; po.bias[1] = bo; po.bias[2] = bo;
    po.C[0] = out; po.C[1] = out; po.C[2] = out;
    dim3 gOut(HIDDEN / TBN, ROWS / TBM, 1);
    gemm_bf16_db_kernel<true><<<gOut, 256, GEMM_SMEM>>>(ctx, po, x);
}